// round 10
// baseline (speedup 1.0000x reference)
#include <cuda_runtime.h>
#include <cuda_bf16.h>
#include <cuda_fp16.h>
#include <cstdint>

#define EPS 1e-6f

// Shapes
#define B_ 4
#define N_ 8192
#define DIM_ 1024
#define H_ 16
#define M_ (B_ * N_)            // 32768 rows
#define BIG (M_ * DIM_)         // 33554432 elems
#define NQKV 3072

// ---------------- scratch (static device globals; no allocation) ----------------
__device__ __half g_xh[BIG], g_xl[BIG];                 // x hi/lo [M,1024] fp16
__device__ float g_qkv[(size_t)M_ * NQKV];              // [M, q|k|v]
__device__ __half g_ah[BIG], g_al[BIG];                 // attn hi/lo [M,1024] fp16
__device__ float g_wqp[DIM_ * DIM_];
__device__ float g_wkp[DIM_ * DIM_];
__device__ __half g_wc[DIM_ * NQKV];                    // combined W [K,3072] fp16
__device__ __half g_wo[DIM_ * DIM_];                    // Wo [K,1024] fp16
__device__ float g_kv[64 * 64 * 64];   // [bh, f, d]
__device__ float g_ksum[64 * 64];      // [bh, f]

// ---------------- helpers ----------------
__device__ __forceinline__ uint32_t smem_u32(const void* p) {
    return (uint32_t)__cvta_generic_to_shared(p);
}

__device__ __forceinline__ void mma16816(float* c, const uint32_t* a, const uint32_t* b) {
    asm volatile(
        "mma.sync.aligned.m16n8k16.row.col.f32.f16.f16.f32 "
        "{%0,%1,%2,%3}, {%4,%5,%6,%7}, {%8,%9}, {%0,%1,%2,%3};\n"
        : "+f"(c[0]), "+f"(c[1]), "+f"(c[2]), "+f"(c[3])
        : "r"(a[0]), "r"(a[1]), "r"(a[2]), "r"(a[3]), "r"(b[0]), "r"(b[1]));
}

__device__ __forceinline__ void ldsm4(uint32_t* r, uint32_t addr) {
    asm volatile("ldmatrix.sync.aligned.m8n8.x4.shared.b16 {%0,%1,%2,%3}, [%4];"
        : "=r"(r[0]), "=r"(r[1]), "=r"(r[2]), "=r"(r[3]) : "r"(addr));
}
__device__ __forceinline__ void ldsm4t(uint32_t* r, uint32_t addr) {
    asm volatile("ldmatrix.sync.aligned.m8n8.x4.trans.shared.b16 {%0,%1,%2,%3}, [%4];"
        : "=r"(r[0]), "=r"(r[1]), "=r"(r[2]), "=r"(r[3]) : "r"(addr));
}

__device__ __forceinline__ void cp16(void* dst, const void* src) {
    asm volatile("cp.async.cg.shared.global [%0], [%1], 16;"
        :: "r"(smem_u32(dst)), "l"(src));
}
__device__ __forceinline__ void cp_commit() {
    asm volatile("cp.async.commit_group;");
}

// split fp32 pair into fp16 hi pair and fp16 lo (residual) pair, packed as u32
__device__ __forceinline__ void split2h(float a, float b, uint32_t& h, uint32_t& l) {
    __half ha = __float2half_rn(a);
    __half hb = __float2half_rn(b);
    __half la = __float2half_rn(a - __half2float(ha));
    __half lb = __float2half_rn(b - __half2float(hb));
    h = (uint32_t)__half_as_ushort(ha) | ((uint32_t)__half_as_ushort(hb) << 16);
    l = (uint32_t)__half_as_ushort(la) | ((uint32_t)__half_as_ushort(lb) << 16);
}
__device__ __forceinline__ uint32_t round2h(float a, float b) {
    return (uint32_t)__half_as_ushort(__float2half_rn(a)) |
           ((uint32_t)__half_as_ushort(__float2half_rn(b)) << 16);
}

// ---------------- split: fp32 -> fp16 hi/lo (contiguous) ----------------
__global__ __launch_bounds__(256) void split_kernel(
    const float* __restrict__ src, __half* __restrict__ h,
    __half* __restrict__ l, int n4)
{
    int i = blockIdx.x * 256 + threadIdx.x;
    if (i < n4) {
        float4 v = ((const float4*)src)[i];
        uint32_t h0, l0, h1, l1;
        split2h(v.x, v.y, h0, l0);
        split2h(v.z, v.w, h1, l1);
        ((uint2*)h)[i] = make_uint2(h0, h1);
        ((uint2*)l)[i] = make_uint2(l0, l1);
    }
}

// ---- round W[1024,1024] fp32 -> fp16 into buffer with leading dim ldout at col c0 ----
__global__ __launch_bounds__(256) void wconv_kernel(
    const float* __restrict__ W, __half* __restrict__ o, int c0, int ldout)
{
    int i = blockIdx.x * 256 + threadIdx.x;   // 262144 float4 tasks
    int r = i >> 8, c4 = (i & 255) << 2;
    float4 v = *(const float4*)(W + (size_t)r * DIM_ + c4);
    uint2 p = make_uint2(round2h(v.x, v.y), round2h(v.z, v.w));
    *(uint2*)(o + (size_t)r * ldout + c0 + c4) = p;
}

// ========== pipelined mma.sync GEMM: C[M, ldc] = A[M,1024] * B[1024, ldb] =======
// fp16x2 scheme: A = hi + lo (fp16), B = fp16-rounded. 2 MMAs per tile-pair.
// BM=128, BN=128, BK=32, 256 threads (8 warps, 4m x 2n), warp tile 32x64.
// 2 CTAs/SM -> 4 warps/SMSP for latency hiding; regs capped at 128.
#define STAGES 3
#define ASTR 40                  // halves per A-smem row
#define A_STG (128 * ASTR)       // 5120 halves
#define B_STG (32 * 128)         // 4096 halves
#define GEMM_SMEM ((size_t)STAGES * (2 * A_STG + B_STG) * 2)   // 86016 B

// EPI: 0 = none, 2 = +bias, 3 = relu+EPS for col<2048 else none
template<int EPI>
__global__ __launch_bounds__(256, 2) void gemm_pipe(
    const __half* __restrict__ Agh, const __half* __restrict__ Agl,
    const __half* __restrict__ Bg,
    float* __restrict__ C, int ldb, int ldc,
    const float* __restrict__ bias)
{
    extern __shared__ __half sm[];
    __half* Ah = sm;
    __half* Al = Ah + STAGES * A_STG;
    __half* Bh = Al + STAGES * A_STG;

    const int tid  = threadIdx.x;
    const int lane = tid & 31;
    const int wid  = tid >> 5;          // 0..7
    const int g    = lane >> 2;
    const int t    = lane & 3;
    const int warp_m = (wid & 3) * 32;  // 0,32,64,96
    const int warp_n = (wid >> 2) * 64; // 0 or 64
    const int mb = blockIdx.y * 128;
    const int nb = blockIdx.x * 128;
    const int K = DIM_;

    float acc[2][8][4];
#pragma unroll
    for (int mi = 0; mi < 2; mi++)
#pragma unroll
        for (int ni = 0; ni < 8; ni++)
#pragma unroll
            for (int c = 0; c < 4; c++) acc[mi][ni][c] = 0.f;

    const int a_row_l  = (lane & 7) + ((lane >> 3) & 1) * 8;
    const int a_koff_l = ((lane >> 4) & 1) * 8;
    const int b_krow_l = (lane & 7) + ((lane >> 3) & 1) * 8;
    const int b_nchk_l = (lane >> 4) & 1;

    const int KT = K >> 5;   // 32

    auto load_stage = [&](int stg, int k0) {
        // A: 1024 x 16B chunks (hi 512 + lo 512): r=0..127, c=0..3
#pragma unroll
        for (int s = 0; s < 4; s++) {
            int j = tid + s * 256;
            int half_ = j >> 9, jj = j & 511;
            int r = jj >> 2, c = jj & 3;
            const __half* src = (half_ ? Agl : Agh) + (size_t)(mb + r) * K + k0 + c * 8;
            __half* dst = (half_ ? Al : Ah) + stg * A_STG + r * ASTR + c * 8;
            cp16(dst, src);
        }
        // B: 512 chunks: kk=0..31, c=0..15 (swizzled)
#pragma unroll
        for (int s = 0; s < 2; s++) {
            int j = tid + s * 256;
            int kk = j >> 4, c = j & 15;
            int cx = c ^ (kk & 7);
            const __half* src = Bg + (size_t)(k0 + kk) * ldb + nb + c * 8;
            __half* dst = Bh + stg * B_STG + kk * 128 + cx * 8;
            cp16(dst, src);
        }
        cp_commit();
    };

    int load_k = 0;
    for (; load_k < STAGES - 1; ++load_k) load_stage(load_k, load_k * 32);

    for (int i = 0; i < KT; i++) {
        asm volatile("cp.async.wait_group %0;" :: "n"(STAGES - 2));
        __syncthreads();
        if (load_k < KT) { load_stage(load_k % STAGES, load_k * 32); load_k++; }

        const int stg = i % STAGES;
        const __half* sAh = Ah + stg * A_STG;
        const __half* sAl = Al + stg * A_STG;
        const __half* sBh = Bh + stg * B_STG;

#pragma unroll
        for (int ks = 0; ks < 2; ks++) {
            const int kb = ks * 16;
            uint32_t ah[2][4], al[2][4];
#pragma unroll
            for (int mi = 0; mi < 2; mi++) {
                int row = warp_m + mi * 16 + a_row_l;
                ldsm4(ah[mi], smem_u32(&sAh[row * ASTR + kb + a_koff_l]));
                ldsm4(al[mi], smem_u32(&sAl[row * ASTR + kb + a_koff_l]));
            }
#pragma unroll
            for (int np = 0; np < 4; np++) {
                const int krow  = kb + b_krow_l;
                const int chunk = ((warp_n + np * 16) >> 3) + b_nchk_l;
                const int cx    = chunk ^ (krow & 7);
                uint32_t bh[2][2], r4[4];
                ldsm4t(r4, smem_u32(&sBh[krow * 128 + cx * 8]));
                bh[0][0] = r4[0]; bh[0][1] = r4[1]; bh[1][0] = r4[2]; bh[1][1] = r4[3];
#pragma unroll
                for (int mi = 0; mi < 2; mi++)
#pragma unroll
                    for (int q = 0; q < 2; q++) {
                        float* a4 = acc[mi][np * 2 + q];
                        mma16816(a4, ah[mi], bh[q]);
                        mma16816(a4, al[mi], bh[q]);
                    }
            }
        }
    }

    // ---- epilogue ----
#pragma unroll
    for (int mi = 0; mi < 2; mi++) {
        int r0 = mb + warp_m + mi * 16 + g;
#pragma unroll
        for (int ni = 0; ni < 8; ni++) {
            int col = nb + warp_n + ni * 8 + 2 * t;
            float2 v0 = make_float2(acc[mi][ni][0], acc[mi][ni][1]);
            float2 v1 = make_float2(acc[mi][ni][2], acc[mi][ni][3]);
            if (EPI == 3) {
                if (col < 2048) {
                    v0.x = fmaxf(v0.x, 0.f) + EPS; v0.y = fmaxf(v0.y, 0.f) + EPS;
                    v1.x = fmaxf(v1.x, 0.f) + EPS; v1.y = fmaxf(v1.y, 0.f) + EPS;
                }
            }
            if (EPI == 2) {
                float b0 = bias[col], b1 = bias[col + 1];
                v0.x += b0; v0.y += b1; v1.x += b0; v1.y += b1;
            }
            *(float2*)(C + (size_t)r0 * ldc + col)       = v0;
            *(float2*)(C + (size_t)(r0 + 8) * ldc + col) = v1;
        }
    }
}

// ---------------- fold: Wp[:, h*64+f] = W[:, h*64+:] @ proj ----------------
__global__ __launch_bounds__(256) void fold_kernel(
    const float* __restrict__ W, const float* __restrict__ proj,
    float* __restrict__ Wp)
{
    const int dblk = blockIdx.x;
    const int h    = blockIdx.y;
    const int tid  = threadIdx.x;

    __shared__ float P[64 * 64];
    __shared__ float Wb[64][65];

#pragma unroll
    for (int s = 0; s < 16; s++) {
        int j = tid + s * 256;
        P[j] = proj[j];
        int r = j >> 6, c = j & 63;
        Wb[r][c] = W[(size_t)(dblk * 64 + r) * DIM_ + h * 64 + c];
    }
    __syncthreads();

    const int f  = tid & 63;
    const int ds = tid >> 6;
    for (int dl = ds; dl < 64; dl += 4) {
        float acc = 0.f;
#pragma unroll 16
        for (int dd = 0; dd < 64; dd++)
            acc = fmaf(Wb[dl][dd], P[dd * 64 + f], acc);
        Wp[(size_t)(dblk * 64 + dl) * DIM_ + h * 64 + f] = acc;
    }
}

// ---------------- zero scratch ----------------
__global__ void zero_kv_kernel()
{
    int i = blockIdx.x * 256 + threadIdx.x;
    if (i < 64 * 64 * 64) g_kv[i] = 0.f;
    if (i < 64 * 64) g_ksum[i] = 0.f;
}

// ---------------- kv[f,d] += sum_n kf[n,f]*v[n,d]; ksum[f] += sum_n kf[n,f] -------
__global__ __launch_bounds__(256) void kv_accum_kernel(
    const float* __restrict__ kf, const float* __restrict__ v, int ld)
{
    const int bh = blockIdx.y;
    const int b = bh >> 4, h = bh & 15;
    const int n0 = blockIdx.x * 512;
    const int tid = threadIdx.x;

    __shared__ float kfs[32][64];
    __shared__ float vs[32][64];

    const int d  = tid & 63;
    const int fg = tid >> 6;

    float acc[16];
#pragma unroll
    for (int i = 0; i < 16; i++) acc[i] = 0.f;
    float ks = 0.f;

    for (int base = 0; base < 512; base += 32) {
#pragma unroll
        for (int s = 0; s < 2; s++) {
            int j = tid + s * 256;
            int r = j >> 4, c4 = (j & 15) << 2;
            size_t row = (size_t)(b * N_ + n0 + base + r);
            *(float4*)&kfs[r][c4] = *(const float4*)(kf + row * ld + h * 64 + c4);
            *(float4*)&vs[r][c4]  = *(const float4*)(v  + row * ld + h * 64 + c4);
        }
        __syncthreads();
#pragma unroll
        for (int r = 0; r < 32; r++) {
            float vd = vs[r][d];
#pragma unroll
            for (int i = 0; i < 16; i++)
                acc[i] = fmaf(kfs[r][fg * 16 + i], vd, acc[i]);
            if (tid < 64) ks += kfs[r][tid];
        }
        __syncthreads();
    }

#pragma unroll
    for (int i = 0; i < 16; i++)
        atomicAdd(&g_kv[(size_t)bh * 4096 + (fg * 16 + i) * 64 + d], acc[i]);
    if (tid < 64) atomicAdd(&g_ksum[bh * 64 + tid], ks);
}

// ---- attn = (qf @ kv) / (qf.ksum + EPS), written directly as fp16 hi/lo ---------
__global__ __launch_bounds__(256) void attn_out_kernel(
    const float* __restrict__ qf, int ld,
    __half* __restrict__ outh, __half* __restrict__ outl)
{
    const int bh = blockIdx.y;
    const int b = bh >> 4, h = bh & 15;
    const int n0 = blockIdx.x * 64;
    const int tid = threadIdx.x;

    __shared__ float KVX[64][68];
    __shared__ float QF[64][68];

#pragma unroll
    for (int s = 0; s < 4; s++) {
        int j = tid + s * 256;
        int f = j >> 4, d4 = (j & 15) << 2;
        *(float4*)&KVX[f][d4] = *(const float4*)(g_kv + (size_t)bh * 4096 + f * 64 + d4);
        *(float4*)&QF[f][d4]  = *(const float4*)(qf + (size_t)(b * N_ + n0 + f) * ld + h * 64 + d4);
    }
    if (tid < 64) KVX[tid][64] = g_ksum[bh * 64 + tid];
    __syncthreads();

    const int d4 = (tid & 15) << 2;
    const int rb = tid >> 4;
#pragma unroll
    for (int p = 0; p < 4; p++) {
        int r = p * 16 + rb;
        float4 num = make_float4(0.f, 0.f, 0.f, 0.f);
        float den = 0.f;
#pragma unroll 16
        for (int f = 0; f < 64; f++) {
            float q = QF[r][f];
            float4 kvv = *(float4*)&KVX[f][d4];
            num.x = fmaf(q, kvv.x, num.x);
            num.y = fmaf(q, kvv.y, num.y);
            num.z = fmaf(q, kvv.z, num.z);
            num.w = fmaf(q, kvv.w, num.w);
            den   = fmaf(q, KVX[f][64], den);
        }
        float inv = 1.f / (den + EPS);
        float4 o = make_float4(num.x * inv, num.y * inv, num.z * inv, num.w * inv);
        uint32_t h0, l0, h1, l1;
        split2h(o.x, o.y, h0, l0);
        split2h(o.z, o.w, h1, l1);
        size_t idx = (size_t)(b * N_ + n0 + r) * DIM_ + h * 64 + d4;
        *(uint2*)(outh + idx) = make_uint2(h0, h1);
        *(uint2*)(outl + idx) = make_uint2(l0, l1);
    }
}

// ---------------- launch ----------------
extern "C" void kernel_launch(void* const* d_in, const int* in_sizes, int n_in,
                              void* d_out, int out_size)
{
    const float* x    = (const float*)d_in[0];
    const float* Wq   = (const float*)d_in[1];
    const float* Wk   = (const float*)d_in[2];
    const float* Wv   = (const float*)d_in[3];
    const float* proj = (const float*)d_in[4];
    const float* Wo   = (const float*)d_in[5];
    const float* bo   = (const float*)d_in[6];
    float* out = (float*)d_out;

    __half *xh, *xl, *ah, *al, *wc, *wo;
    float *qkv, *wqp, *wkp;
    cudaGetSymbolAddress((void**)&xh,  g_xh);
    cudaGetSymbolAddress((void**)&xl,  g_xl);
    cudaGetSymbolAddress((void**)&qkv, g_qkv);
    cudaGetSymbolAddress((void**)&ah,  g_ah);
    cudaGetSymbolAddress((void**)&al,  g_al);
    cudaGetSymbolAddress((void**)&wqp, g_wqp);
    cudaGetSymbolAddress((void**)&wkp, g_wkp);
    cudaGetSymbolAddress((void**)&wc,  g_wc);
    cudaGetSymbolAddress((void**)&wo,  g_wo);

    cudaFuncSetAttribute(gemm_pipe<2>, cudaFuncAttributeMaxDynamicSharedMemorySize, GEMM_SMEM);
    cudaFuncSetAttribute(gemm_pipe<3>, cudaFuncAttributeMaxDynamicSharedMemorySize, GEMM_SMEM);

    // fold proj into Wq / Wk
    dim3 fold_grid(16, 16);
    fold_kernel<<<fold_grid, 256>>>(Wq, proj, wqp);
    fold_kernel<<<fold_grid, 256>>>(Wk, proj, wkp);

    // convert operands: x split fp16 hi/lo; weights rounded to fp16
    split_kernel<<<BIG / 4 / 256, 256>>>(x, xh, xl, BIG / 4);
    const int W4 = DIM_ * DIM_ / 4;
    wconv_kernel<<<W4 / 256, 256>>>(wqp, wc, 0,    NQKV);
    wconv_kernel<<<W4 / 256, 256>>>(wkp, wc, 1024, NQKV);
    wconv_kernel<<<W4 / 256, 256>>>(Wv,  wc, 2048, NQKV);
    wconv_kernel<<<W4 / 256, 256>>>(Wo,  wo, 0,    DIM_);

    // merged QKV GEMM: qkv[M,3072] = x @ [Wqp | Wkp | Wv], relu+eps on q,k cols
    dim3 gq(NQKV / 128, M_ / 128);   // (24, 256)
    gemm_pipe<3><<<gq, 256, GEMM_SMEM>>>(xh, xl, wc, qkv, NQKV, NQKV, nullptr);

    // kv + ksum reduction (kf = cols 1024.., v = cols 2048..)
    zero_kv_kernel<<<1024, 256>>>();
    kv_accum_kernel<<<dim3(16, 64), 256>>>(qkv + 1024, qkv + 2048, NQKV);

    // numerator / denominator -> fp16 hi/lo directly (qf = cols 0..)
    attn_out_kernel<<<dim3(128, 64), 256>>>(qkv, NQKV, ah, al);

    // output projection + bias
    dim3 go(DIM_ / 128, M_ / 128);   // (8, 256)
    gemm_pipe<2><<<go, 256, GEMM_SMEM>>>(ah, al, wo, out, DIM_, DIM_, bo);
}

// round 11
// speedup vs baseline: 1.0645x; 1.0645x over previous
#include <cuda_runtime.h>
#include <cuda_bf16.h>
#include <cuda_fp16.h>
#include <cstdint>

#define EPS 1e-6f

// Shapes
#define B_ 4
#define N_ 8192
#define DIM_ 1024
#define H_ 16
#define M_ (B_ * N_)            // 32768 rows
#define BIG (M_ * DIM_)         // 33554432 elems
#define NQKV 3072

// ---------------- scratch (static device globals; no allocation) ----------------
__device__ __half g_xh[BIG], g_xl[BIG];                 // x hi/lo [M,1024] fp16
__device__ float g_qkv[(size_t)M_ * NQKV];              // [M, q|k|v]
__device__ __half g_ah[BIG];                            // attn fp16 [M,1024]
__device__ float g_wqp[DIM_ * DIM_];
__device__ float g_wkp[DIM_ * DIM_];
__device__ __half g_wc[DIM_ * NQKV];                    // combined W [K,3072] fp16
__device__ __half g_wo[DIM_ * DIM_];                    // Wo [K,1024] fp16
__device__ float g_kv[64 * 64 * 64];   // [bh, f, d]
__device__ float g_ksum[64 * 64];      // [bh, f]

// ---------------- helpers ----------------
__device__ __forceinline__ uint32_t smem_u32(const void* p) {
    return (uint32_t)__cvta_generic_to_shared(p);
}

__device__ __forceinline__ void mma16816(float* c, const uint32_t* a, const uint32_t* b) {
    asm volatile(
        "mma.sync.aligned.m16n8k16.row.col.f32.f16.f16.f32 "
        "{%0,%1,%2,%3}, {%4,%5,%6,%7}, {%8,%9}, {%0,%1,%2,%3};\n"
        : "+f"(c[0]), "+f"(c[1]), "+f"(c[2]), "+f"(c[3])
        : "r"(a[0]), "r"(a[1]), "r"(a[2]), "r"(a[3]), "r"(b[0]), "r"(b[1]));
}

__device__ __forceinline__ void ldsm4(uint32_t* r, uint32_t addr) {
    asm volatile("ldmatrix.sync.aligned.m8n8.x4.shared.b16 {%0,%1,%2,%3}, [%4];"
        : "=r"(r[0]), "=r"(r[1]), "=r"(r[2]), "=r"(r[3]) : "r"(addr));
}
__device__ __forceinline__ void ldsm4t(uint32_t* r, uint32_t addr) {
    asm volatile("ldmatrix.sync.aligned.m8n8.x4.trans.shared.b16 {%0,%1,%2,%3}, [%4];"
        : "=r"(r[0]), "=r"(r[1]), "=r"(r[2]), "=r"(r[3]) : "r"(addr));
}

__device__ __forceinline__ void cp16(void* dst, const void* src) {
    asm volatile("cp.async.cg.shared.global [%0], [%1], 16;"
        :: "r"(smem_u32(dst)), "l"(src));
}
__device__ __forceinline__ void cp_commit() {
    asm volatile("cp.async.commit_group;");
}

// split fp32 pair into fp16 hi pair and fp16 lo (residual) pair, packed as u32
__device__ __forceinline__ void split2h(float a, float b, uint32_t& h, uint32_t& l) {
    __half ha = __float2half_rn(a);
    __half hb = __float2half_rn(b);
    __half la = __float2half_rn(a - __half2float(ha));
    __half lb = __float2half_rn(b - __half2float(hb));
    h = (uint32_t)__half_as_ushort(ha) | ((uint32_t)__half_as_ushort(hb) << 16);
    l = (uint32_t)__half_as_ushort(la) | ((uint32_t)__half_as_ushort(lb) << 16);
}
__device__ __forceinline__ uint32_t round2h(float a, float b) {
    return (uint32_t)__half_as_ushort(__float2half_rn(a)) |
           ((uint32_t)__half_as_ushort(__float2half_rn(b)) << 16);
}

// ---------------- split: fp32 -> fp16 hi/lo (4 float4 per thread, MLP=4) --------
__global__ __launch_bounds__(256) void split_kernel(
    const float* __restrict__ src, __half* __restrict__ h,
    __half* __restrict__ l, int n4)
{
    int base = (blockIdx.x * 256 + threadIdx.x) * 4;
    if (base + 3 < n4) {
        float4 v0 = ((const float4*)src)[base + 0];
        float4 v1 = ((const float4*)src)[base + 1];
        float4 v2 = ((const float4*)src)[base + 2];
        float4 v3 = ((const float4*)src)[base + 3];
        uint32_t ha, la, hb, lb;
#define DO1(idx, vv) \
        split2h(vv.x, vv.y, ha, la); split2h(vv.z, vv.w, hb, lb); \
        ((uint2*)h)[base + idx] = make_uint2(ha, hb); \
        ((uint2*)l)[base + idx] = make_uint2(la, lb);
        DO1(0, v0) DO1(1, v1) DO1(2, v2) DO1(3, v3)
#undef DO1
    }
}

// ---- round W[1024,1024] fp32 -> fp16 into buffer with leading dim ldout at col c0 ----
__global__ __launch_bounds__(256) void wconv_kernel(
    const float* __restrict__ W, __half* __restrict__ o, int c0, int ldout)
{
    int i = blockIdx.x * 256 + threadIdx.x;   // 262144 float4 tasks
    int r = i >> 8, c4 = (i & 255) << 2;
    float4 v = *(const float4*)(W + (size_t)r * DIM_ + c4);
    uint2 p = make_uint2(round2h(v.x, v.y), round2h(v.z, v.w));
    *(uint2*)(o + (size_t)r * ldout + c0 + c4) = p;
}

// ========== pipelined mma.sync GEMM: C[M, ldc] = A[M,1024] * B[1024, ldb] =======
// fp16 scheme: A = hi (+ lo if AL), B = fp16-rounded.
// BM=128, BN=128, BK=32, 128 threads (4 warps 2x2), warp tile 64x64, 3 stages.
#define STAGES 3
#define ASTR 40                  // halves per A-smem row
#define A_STG (128 * ASTR)       // 5120 halves
#define B_STG (32 * 128)         // 4096 halves
#define GEMM_SMEM ((size_t)STAGES * (2 * A_STG + B_STG) * 2)   // 86016 B

// EPI: 0 = none, 2 = +bias, 3 = relu+EPS for col<2048 else none
// AL: 1 = A has lo residual pass, 0 = single fp16 A
template<int EPI, int AL>
__global__ __launch_bounds__(128, 2) void gemm_pipe(
    const __half* __restrict__ Agh, const __half* __restrict__ Agl,
    const __half* __restrict__ Bg,
    float* __restrict__ C, int ldb, int ldc,
    const float* __restrict__ bias)
{
    extern __shared__ __half sm[];
    __half* Ah = sm;
    __half* Al = Ah + STAGES * A_STG;
    __half* Bh = Al + STAGES * A_STG;

    const int tid  = threadIdx.x;
    const int lane = tid & 31;
    const int wid  = tid >> 5;          // 0..3
    const int g    = lane >> 2;
    const int t    = lane & 3;
    const int warp_m = (wid & 1) * 64;  // 0 or 64
    const int warp_n = (wid >> 1) * 64; // 0 or 64
    const int mb = blockIdx.y * 128;
    const int nb = blockIdx.x * 128;
    const int K = DIM_;

    float acc[4][8][4];
#pragma unroll
    for (int mi = 0; mi < 4; mi++)
#pragma unroll
        for (int ni = 0; ni < 8; ni++)
#pragma unroll
            for (int c = 0; c < 4; c++) acc[mi][ni][c] = 0.f;

    const int a_row_l  = (lane & 7) + ((lane >> 3) & 1) * 8;
    const int a_koff_l = ((lane >> 4) & 1) * 8;
    const int b_krow_l = (lane & 7) + ((lane >> 3) & 1) * 8;
    const int b_nchk_l = (lane >> 4) & 1;

    const int KT = K >> 5;   // 32

    auto load_stage = [&](int stg, int k0) {
        // A-hi: 512 x 16B chunks: r=0..127, c=0..3
#pragma unroll
        for (int s = 0; s < 4; s++) {
            int j = tid + s * 128;
            int r = j >> 2, c = j & 3;
            cp16(Ah + stg * A_STG + r * ASTR + c * 8,
                 Agh + (size_t)(mb + r) * K + k0 + c * 8);
        }
        if (AL) {
#pragma unroll
            for (int s = 0; s < 4; s++) {
                int j = tid + s * 128;
                int r = j >> 2, c = j & 3;
                cp16(Al + stg * A_STG + r * ASTR + c * 8,
                     Agl + (size_t)(mb + r) * K + k0 + c * 8);
            }
        }
        // B: 512 chunks: kk=0..31, c=0..15 (swizzled)
#pragma unroll
        for (int s = 0; s < 4; s++) {
            int j = tid + s * 128;
            int kk = j >> 4, c = j & 15;
            int cx = c ^ (kk & 7);
            cp16(Bh + stg * B_STG + kk * 128 + cx * 8,
                 Bg + (size_t)(k0 + kk) * ldb + nb + c * 8);
        }
        cp_commit();
    };

    int load_k = 0;
    for (; load_k < STAGES - 1; ++load_k) load_stage(load_k, load_k * 32);

    for (int i = 0; i < KT; i++) {
        asm volatile("cp.async.wait_group %0;" :: "n"(STAGES - 2));
        __syncthreads();
        if (load_k < KT) { load_stage(load_k % STAGES, load_k * 32); load_k++; }

        const int stg = i % STAGES;
        const __half* sAh = Ah + stg * A_STG;
        const __half* sAl = Al + stg * A_STG;
        const __half* sBh = Bh + stg * B_STG;

#pragma unroll
        for (int ks = 0; ks < 2; ks++) {
            const int kb = ks * 16;
            uint32_t ah[4][4], al[4][4];
#pragma unroll
            for (int mi = 0; mi < 4; mi++) {
                int row = warp_m + mi * 16 + a_row_l;
                ldsm4(ah[mi], smem_u32(&sAh[row * ASTR + kb + a_koff_l]));
                if (AL) ldsm4(al[mi], smem_u32(&sAl[row * ASTR + kb + a_koff_l]));
            }
#pragma unroll
            for (int np = 0; np < 4; np++) {
                const int krow  = kb + b_krow_l;
                const int chunk = ((warp_n + np * 16) >> 3) + b_nchk_l;
                const int cx    = chunk ^ (krow & 7);
                uint32_t bh[2][2], r4[4];
                ldsm4t(r4, smem_u32(&sBh[krow * 128 + cx * 8]));
                bh[0][0] = r4[0]; bh[0][1] = r4[1]; bh[1][0] = r4[2]; bh[1][1] = r4[3];
#pragma unroll
                for (int mi = 0; mi < 4; mi++)
#pragma unroll
                    for (int q = 0; q < 2; q++) {
                        float* a4 = acc[mi][np * 2 + q];
                        mma16816(a4, ah[mi], bh[q]);
                        if (AL) mma16816(a4, al[mi], bh[q]);
                    }
            }
        }
    }

    // ---- epilogue ----
#pragma unroll
    for (int mi = 0; mi < 4; mi++) {
        int r0 = mb + warp_m + mi * 16 + g;
#pragma unroll
        for (int ni = 0; ni < 8; ni++) {
            int col = nb + warp_n + ni * 8 + 2 * t;
            float2 v0 = make_float2(acc[mi][ni][0], acc[mi][ni][1]);
            float2 v1 = make_float2(acc[mi][ni][2], acc[mi][ni][3]);
            if (EPI == 3) {
                if (col < 2048) {
                    v0.x = fmaxf(v0.x, 0.f) + EPS; v0.y = fmaxf(v0.y, 0.f) + EPS;
                    v1.x = fmaxf(v1.x, 0.f) + EPS; v1.y = fmaxf(v1.y, 0.f) + EPS;
                }
            }
            if (EPI == 2) {
                float b0 = bias[col], b1 = bias[col + 1];
                v0.x += b0; v0.y += b1; v1.x += b0; v1.y += b1;
            }
            *(float2*)(C + (size_t)r0 * ldc + col)       = v0;
            *(float2*)(C + (size_t)(r0 + 8) * ldc + col) = v1;
        }
    }
}

// ---------------- fold: Wp[:, h*64+f] = W[:, h*64+:] @ proj ----------------
__global__ __launch_bounds__(256) void fold_kernel(
    const float* __restrict__ W, const float* __restrict__ proj,
    float* __restrict__ Wp)
{
    const int dblk = blockIdx.x;
    const int h    = blockIdx.y;
    const int tid  = threadIdx.x;

    __shared__ float P[64 * 64];
    __shared__ float Wb[64][65];

#pragma unroll
    for (int s = 0; s < 16; s++) {
        int j = tid + s * 256;
        P[j] = proj[j];
        int r = j >> 6, c = j & 63;
        Wb[r][c] = W[(size_t)(dblk * 64 + r) * DIM_ + h * 64 + c];
    }
    __syncthreads();

    const int f  = tid & 63;
    const int ds = tid >> 6;
    for (int dl = ds; dl < 64; dl += 4) {
        float acc = 0.f;
#pragma unroll 16
        for (int dd = 0; dd < 64; dd++)
            acc = fmaf(Wb[dl][dd], P[dd * 64 + f], acc);
        Wp[(size_t)(dblk * 64 + dl) * DIM_ + h * 64 + f] = acc;
    }
}

// ---------------- zero scratch ----------------
__global__ void zero_kv_kernel()
{
    int i = blockIdx.x * 256 + threadIdx.x;
    if (i < 64 * 64 * 64) g_kv[i] = 0.f;
    if (i < 64 * 64) g_ksum[i] = 0.f;
}

// ---------------- kv[f,d] += sum_n kf[n,f]*v[n,d]; ksum[f] += sum_n kf[n,f] -------
__global__ __launch_bounds__(256) void kv_accum_kernel(
    const float* __restrict__ kf, const float* __restrict__ v, int ld)
{
    const int bh = blockIdx.y;
    const int b = bh >> 4, h = bh & 15;
    const int n0 = blockIdx.x * 1024;
    const int tid = threadIdx.x;

    __shared__ float kfs[32][64];
    __shared__ float vs[32][64];

    const int d  = tid & 63;
    const int fg = tid >> 6;

    float acc[16];
#pragma unroll
    for (int i = 0; i < 16; i++) acc[i] = 0.f;
    float ks = 0.f;

    for (int base = 0; base < 1024; base += 32) {
#pragma unroll
        for (int s = 0; s < 2; s++) {
            int j = tid + s * 256;
            int r = j >> 4, c4 = (j & 15) << 2;
            size_t row = (size_t)(b * N_ + n0 + base + r);
            *(float4*)&kfs[r][c4] = *(const float4*)(kf + row * ld + h * 64 + c4);
            *(float4*)&vs[r][c4]  = *(const float4*)(v  + row * ld + h * 64 + c4);
        }
        __syncthreads();
#pragma unroll
        for (int r = 0; r < 32; r++) {
            float vd = vs[r][d];
#pragma unroll
            for (int i = 0; i < 16; i++)
                acc[i] = fmaf(kfs[r][fg * 16 + i], vd, acc[i]);
            if (tid < 64) ks += kfs[r][tid];
        }
        __syncthreads();
    }

#pragma unroll
    for (int i = 0; i < 16; i++)
        atomicAdd(&g_kv[(size_t)bh * 4096 + (fg * 16 + i) * 64 + d], acc[i]);
    if (tid < 64) atomicAdd(&g_ksum[bh * 64 + tid], ks);
}

// ---- attn = (qf @ kv) / (qf.ksum + EPS), written directly as single fp16 --------
__global__ __launch_bounds__(256) void attn_out_kernel(
    const float* __restrict__ qf, int ld,
    __half* __restrict__ outh)
{
    const int bh = blockIdx.y;
    const int b = bh >> 4, h = bh & 15;
    const int n0 = blockIdx.x * 64;
    const int tid = threadIdx.x;

    __shared__ float KVX[64][68];
    __shared__ float QF[64][68];

#pragma unroll
    for (int s = 0; s < 4; s++) {
        int j = tid + s * 256;
        int f = j >> 4, d4 = (j & 15) << 2;
        *(float4*)&KVX[f][d4] = *(const float4*)(g_kv + (size_t)bh * 4096 + f * 64 + d4);
        *(float4*)&QF[f][d4]  = *(const float4*)(qf + (size_t)(b * N_ + n0 + f) * ld + h * 64 + d4);
    }
    if (tid < 64) KVX[tid][64] = g_ksum[bh * 64 + tid];
    __syncthreads();

    const int d4 = (tid & 15) << 2;
    const int rb = tid >> 4;
#pragma unroll
    for (int p = 0; p < 4; p++) {
        int r = p * 16 + rb;
        float4 num = make_float4(0.f, 0.f, 0.f, 0.f);
        float den = 0.f;
#pragma unroll 16
        for (int f = 0; f < 64; f++) {
            float q = QF[r][f];
            float4 kvv = *(float4*)&KVX[f][d4];
            num.x = fmaf(q, kvv.x, num.x);
            num.y = fmaf(q, kvv.y, num.y);
            num.z = fmaf(q, kvv.z, num.z);
            num.w = fmaf(q, kvv.w, num.w);
            den   = fmaf(q, KVX[f][64], den);
        }
        float inv = 1.f / (den + EPS);
        uint2 p2 = make_uint2(round2h(num.x * inv, num.y * inv),
                              round2h(num.z * inv, num.w * inv));
        size_t idx = (size_t)(b * N_ + n0 + r) * DIM_ + h * 64 + d4;
        *(uint2*)(outh + idx) = p2;
    }
}

// ---------------- launch ----------------
extern "C" void kernel_launch(void* const* d_in, const int* in_sizes, int n_in,
                              void* d_out, int out_size)
{
    const float* x    = (const float*)d_in[0];
    const float* Wq   = (const float*)d_in[1];
    const float* Wk   = (const float*)d_in[2];
    const float* Wv   = (const float*)d_in[3];
    const float* proj = (const float*)d_in[4];
    const float* Wo   = (const float*)d_in[5];
    const float* bo   = (const float*)d_in[6];
    float* out = (float*)d_out;

    __half *xh, *xl, *ah, *wc, *wo;
    float *qkv, *wqp, *wkp;
    cudaGetSymbolAddress((void**)&xh,  g_xh);
    cudaGetSymbolAddress((void**)&xl,  g_xl);
    cudaGetSymbolAddress((void**)&qkv, g_qkv);
    cudaGetSymbolAddress((void**)&ah,  g_ah);
    cudaGetSymbolAddress((void**)&wqp, g_wqp);
    cudaGetSymbolAddress((void**)&wkp, g_wkp);
    cudaGetSymbolAddress((void**)&wc,  g_wc);
    cudaGetSymbolAddress((void**)&wo,  g_wo);

    cudaFuncSetAttribute((const void*)gemm_pipe<3,1>,
                         cudaFuncAttributeMaxDynamicSharedMemorySize, GEMM_SMEM);
    cudaFuncSetAttribute((const void*)gemm_pipe<2,0>,
                         cudaFuncAttributeMaxDynamicSharedMemorySize, GEMM_SMEM);

    // fold proj into Wq / Wk
    dim3 fold_grid(16, 16);
    fold_kernel<<<fold_grid, 256>>>(Wq, proj, wqp);
    fold_kernel<<<fold_grid, 256>>>(Wk, proj, wkp);

    // convert operands: x split fp16 hi/lo; weights rounded to fp16
    split_kernel<<<BIG / 16 / 256, 256>>>(x, xh, xl, BIG / 4);
    const int W4 = DIM_ * DIM_ / 4;
    wconv_kernel<<<W4 / 256, 256>>>(wqp, wc, 0,    NQKV);
    wconv_kernel<<<W4 / 256, 256>>>(wkp, wc, 1024, NQKV);
    wconv_kernel<<<W4 / 256, 256>>>(Wv,  wc, 2048, NQKV);
    wconv_kernel<<<W4 / 256, 256>>>(Wo,  wo, 0,    DIM_);

    // merged QKV GEMM: qkv[M,3072] = x @ [Wqp | Wkp | Wv], relu+eps on q,k cols
    dim3 gq(NQKV / 128, M_ / 128);   // (24, 256)
    gemm_pipe<3,1><<<gq, 128, GEMM_SMEM>>>(xh, xl, wc, qkv, NQKV, NQKV, nullptr);

    // kv + ksum reduction (kf = cols 1024.., v = cols 2048..)
    zero_kv_kernel<<<1024, 256>>>();
    kv_accum_kernel<<<dim3(8, 64), 256>>>(qkv + 1024, qkv + 2048, NQKV);

    // numerator / denominator -> single fp16 attn
    attn_out_kernel<<<dim3(128, 64), 256>>>(qkv, NQKV, ah);

    // output projection + bias (single-precision A pass)
    dim3 go(DIM_ / 128, M_ / 128);   // (8, 256)
    gemm_pipe<2,0><<<go, 128, GEMM_SMEM>>>(ah, nullptr, wo, out, DIM_, DIM_, bo);
}

// round 12
// speedup vs baseline: 1.0946x; 1.0282x over previous
#include <cuda_runtime.h>
#include <cuda_bf16.h>
#include <cuda_fp16.h>
#include <cstdint>

#define EPS 1e-6f

// Shapes
#define B_ 4
#define N_ 8192
#define DIM_ 1024
#define H_ 16
#define M_ (B_ * N_)            // 32768 rows
#define BIG (M_ * DIM_)         // 33554432 elems
#define NQKV 3072

// ---------------- scratch (static device globals; no allocation) ----------------
__device__ __half g_xh[BIG], g_xl[BIG];                 // x hi/lo [M,1024] fp16
__device__ __half g_qkv[(size_t)M_ * NQKV];             // [M, q|k|v] fp16
__device__ __half g_ah[BIG];                            // attn fp16 [M,1024]
__device__ float g_wqp[DIM_ * DIM_];
__device__ float g_wkp[DIM_ * DIM_];
__device__ __half g_wc[DIM_ * NQKV];                    // combined W [K,3072] fp16
__device__ __half g_wo[DIM_ * DIM_];                    // Wo [K,1024] fp16
__device__ float g_kv[64 * 64 * 64];   // [bh, f, d]
__device__ float g_ksum[64 * 64];      // [bh, f]

// ---------------- helpers ----------------
__device__ __forceinline__ uint32_t smem_u32(const void* p) {
    return (uint32_t)__cvta_generic_to_shared(p);
}

__device__ __forceinline__ void mma16816(float* c, const uint32_t* a, const uint32_t* b) {
    asm volatile(
        "mma.sync.aligned.m16n8k16.row.col.f32.f16.f16.f32 "
        "{%0,%1,%2,%3}, {%4,%5,%6,%7}, {%8,%9}, {%0,%1,%2,%3};\n"
        : "+f"(c[0]), "+f"(c[1]), "+f"(c[2]), "+f"(c[3])
        : "r"(a[0]), "r"(a[1]), "r"(a[2]), "r"(a[3]), "r"(b[0]), "r"(b[1]));
}

__device__ __forceinline__ void ldsm4(uint32_t* r, uint32_t addr) {
    asm volatile("ldmatrix.sync.aligned.m8n8.x4.shared.b16 {%0,%1,%2,%3}, [%4];"
        : "=r"(r[0]), "=r"(r[1]), "=r"(r[2]), "=r"(r[3]) : "r"(addr));
}
__device__ __forceinline__ void ldsm4t(uint32_t* r, uint32_t addr) {
    asm volatile("ldmatrix.sync.aligned.m8n8.x4.trans.shared.b16 {%0,%1,%2,%3}, [%4];"
        : "=r"(r[0]), "=r"(r[1]), "=r"(r[2]), "=r"(r[3]) : "r"(addr));
}

__device__ __forceinline__ void cp16(void* dst, const void* src) {
    asm volatile("cp.async.cg.shared.global [%0], [%1], 16;"
        :: "r"(smem_u32(dst)), "l"(src));
}
__device__ __forceinline__ void cp_commit() {
    asm volatile("cp.async.commit_group;");
}

// split fp32 pair into fp16 hi pair and fp16 lo (residual) pair, packed as u32
__device__ __forceinline__ void split2h(float a, float b, uint32_t& h, uint32_t& l) {
    __half ha = __float2half_rn(a);
    __half hb = __float2half_rn(b);
    __half la = __float2half_rn(a - __half2float(ha));
    __half lb = __float2half_rn(b - __half2float(hb));
    h = (uint32_t)__half_as_ushort(ha) | ((uint32_t)__half_as_ushort(hb) << 16);
    l = (uint32_t)__half_as_ushort(la) | ((uint32_t)__half_as_ushort(lb) << 16);
}
__device__ __forceinline__ uint32_t round2h(float a, float b) {
    return (uint32_t)__half_as_ushort(__float2half_rn(a)) |
           ((uint32_t)__half_as_ushort(__float2half_rn(b)) << 16);
}

// ---------------- split: fp32 -> fp16 hi/lo (4 float4 per thread, MLP=4) --------
__global__ __launch_bounds__(256) void split_kernel(
    const float* __restrict__ src, __half* __restrict__ h,
    __half* __restrict__ l, int n4)
{
    int base = (blockIdx.x * 256 + threadIdx.x) * 4;
    if (base + 3 < n4) {
        float4 v0 = ((const float4*)src)[base + 0];
        float4 v1 = ((const float4*)src)[base + 1];
        float4 v2 = ((const float4*)src)[base + 2];
        float4 v3 = ((const float4*)src)[base + 3];
        uint32_t ha, la, hb, lb;
#define DO1(idx, vv) \
        split2h(vv.x, vv.y, ha, la); split2h(vv.z, vv.w, hb, lb); \
        ((uint2*)h)[base + idx] = make_uint2(ha, hb); \
        ((uint2*)l)[base + idx] = make_uint2(la, lb);
        DO1(0, v0) DO1(1, v1) DO1(2, v2) DO1(3, v3)
#undef DO1
    }
}

// ---- round W[1024,1024] fp32 -> fp16 into buffer with leading dim ldout at col c0 ----
__global__ __launch_bounds__(256) void wconv_kernel(
    const float* __restrict__ W, __half* __restrict__ o, int c0, int ldout)
{
    int i = blockIdx.x * 256 + threadIdx.x;   // 262144 float4 tasks
    int r = i >> 8, c4 = (i & 255) << 2;
    float4 v = *(const float4*)(W + (size_t)r * DIM_ + c4);
    uint2 p = make_uint2(round2h(v.x, v.y), round2h(v.z, v.w));
    *(uint2*)(o + (size_t)r * ldout + c0 + c4) = p;
}

// ========== pipelined mma.sync GEMM: C[M, ldc] = A[M,1024] * B[1024, ldb] =======
// fp16 scheme: A = hi (+ lo per-block), B = fp16-rounded.
// BM=128, BN=128, BK=32, 128 threads (4 warps 2x2), warp tile 64x64, 3 stages.
#define STAGES 3
#define ASTR 40                  // halves per A-smem row
#define A_STG (128 * ASTR)       // 5120 halves
#define B_STG (32 * 128)         // 4096 halves
#define GEMM_SMEM ((size_t)STAGES * (2 * A_STG + B_STG) * 2)   // 86016 B

// EPI: 2 = fp32 out + bias, 3 = fp16 out, relu+EPS for col<2048
// AL: 1 = A-lo machinery present (runtime-skipped for v block), 0 = absent
template<int EPI, int AL>
__global__ __launch_bounds__(128, 2) void gemm_pipe(
    const __half* __restrict__ Agh, const __half* __restrict__ Agl,
    const __half* __restrict__ Bg,
    void* __restrict__ Cv, int ldb, int ldc,
    const float* __restrict__ bias)
{
    extern __shared__ __half sm[];
    __half* Ah = sm;
    __half* Al = Ah + STAGES * A_STG;
    __half* Bh = Al + STAGES * A_STG;

    const int tid  = threadIdx.x;
    const int lane = tid & 31;
    const int wid  = tid >> 5;          // 0..3
    const int g    = lane >> 2;
    const int t    = lane & 3;
    const int warp_m = (wid & 1) * 64;  // 0 or 64
    const int warp_n = (wid >> 1) * 64; // 0 or 64
    const int mb = blockIdx.y * 128;
    const int nb = blockIdx.x * 128;
    const int K = DIM_;
    // v block (cols >= 2048) skips the A-lo pass: x-rounding error flows
    // linearly into kv and stays ~2.4e-4 relative.
    const bool use_al = AL && !(EPI == 3 && nb >= 2048);

    float acc[4][8][4];
#pragma unroll
    for (int mi = 0; mi < 4; mi++)
#pragma unroll
        for (int ni = 0; ni < 8; ni++)
#pragma unroll
            for (int c = 0; c < 4; c++) acc[mi][ni][c] = 0.f;

    const int a_row_l  = (lane & 7) + ((lane >> 3) & 1) * 8;
    const int a_koff_l = ((lane >> 4) & 1) * 8;
    const int b_krow_l = (lane & 7) + ((lane >> 3) & 1) * 8;
    const int b_nchk_l = (lane >> 4) & 1;

    const int KT = K >> 5;   // 32

    auto load_stage = [&](int stg, int k0) {
#pragma unroll
        for (int s = 0; s < 4; s++) {
            int j = tid + s * 128;
            int r = j >> 2, c = j & 3;
            cp16(Ah + stg * A_STG + r * ASTR + c * 8,
                 Agh + (size_t)(mb + r) * K + k0 + c * 8);
        }
        if (use_al) {
#pragma unroll
            for (int s = 0; s < 4; s++) {
                int j = tid + s * 128;
                int r = j >> 2, c = j & 3;
                cp16(Al + stg * A_STG + r * ASTR + c * 8,
                     Agl + (size_t)(mb + r) * K + k0 + c * 8);
            }
        }
#pragma unroll
        for (int s = 0; s < 4; s++) {
            int j = tid + s * 128;
            int kk = j >> 4, c = j & 15;
            int cx = c ^ (kk & 7);
            cp16(Bh + stg * B_STG + kk * 128 + cx * 8,
                 Bg + (size_t)(k0 + kk) * ldb + nb + c * 8);
        }
        cp_commit();
    };

    int load_k = 0;
    for (; load_k < STAGES - 1; ++load_k) load_stage(load_k, load_k * 32);

    for (int i = 0; i < KT; i++) {
        asm volatile("cp.async.wait_group %0;" :: "n"(STAGES - 2));
        __syncthreads();
        if (load_k < KT) { load_stage(load_k % STAGES, load_k * 32); load_k++; }

        const int stg = i % STAGES;
        const __half* sAh = Ah + stg * A_STG;
        const __half* sAl = Al + stg * A_STG;
        const __half* sBh = Bh + stg * B_STG;

#pragma unroll
        for (int ks = 0; ks < 2; ks++) {
            const int kb = ks * 16;
            uint32_t ah[4][4], al[4][4];
#pragma unroll
            for (int mi = 0; mi < 4; mi++) {
                int row = warp_m + mi * 16 + a_row_l;
                ldsm4(ah[mi], smem_u32(&sAh[row * ASTR + kb + a_koff_l]));
                if (use_al) ldsm4(al[mi], smem_u32(&sAl[row * ASTR + kb + a_koff_l]));
            }
#pragma unroll
            for (int np = 0; np < 4; np++) {
                const int krow  = kb + b_krow_l;
                const int chunk = ((warp_n + np * 16) >> 3) + b_nchk_l;
                const int cx    = chunk ^ (krow & 7);
                uint32_t bh[2][2], r4[4];
                ldsm4t(r4, smem_u32(&sBh[krow * 128 + cx * 8]));
                bh[0][0] = r4[0]; bh[0][1] = r4[1]; bh[1][0] = r4[2]; bh[1][1] = r4[3];
#pragma unroll
                for (int mi = 0; mi < 4; mi++)
#pragma unroll
                    for (int q = 0; q < 2; q++) {
                        float* a4 = acc[mi][np * 2 + q];
                        mma16816(a4, ah[mi], bh[q]);
                        if (use_al) mma16816(a4, al[mi], bh[q]);
                    }
            }
        }
    }

    // ---- epilogue ----
#pragma unroll
    for (int mi = 0; mi < 4; mi++) {
        int r0 = mb + warp_m + mi * 16 + g;
#pragma unroll
        for (int ni = 0; ni < 8; ni++) {
            int col = nb + warp_n + ni * 8 + 2 * t;
            float2 v0 = make_float2(acc[mi][ni][0], acc[mi][ni][1]);
            float2 v1 = make_float2(acc[mi][ni][2], acc[mi][ni][3]);
            if (EPI == 3) {
                if (col < 2048) {
                    v0.x = fmaxf(v0.x, 0.f) + EPS; v0.y = fmaxf(v0.y, 0.f) + EPS;
                    v1.x = fmaxf(v1.x, 0.f) + EPS; v1.y = fmaxf(v1.y, 0.f) + EPS;
                }
                __half* Ch = (__half*)Cv;
                *(uint32_t*)(Ch + (size_t)r0 * ldc + col)       = round2h(v0.x, v0.y);
                *(uint32_t*)(Ch + (size_t)(r0 + 8) * ldc + col) = round2h(v1.x, v1.y);
            } else {
                float* C = (float*)Cv;
                float b0 = bias[col], b1 = bias[col + 1];
                v0.x += b0; v0.y += b1; v1.x += b0; v1.y += b1;
                *(float2*)(C + (size_t)r0 * ldc + col)       = v0;
                *(float2*)(C + (size_t)(r0 + 8) * ldc + col) = v1;
            }
        }
    }
}

// ---------------- fold: Wp[:, h*64+f] = W[:, h*64+:] @ proj ----------------
__global__ __launch_bounds__(256) void fold_kernel(
    const float* __restrict__ W, const float* __restrict__ proj,
    float* __restrict__ Wp)
{
    const int dblk = blockIdx.x;
    const int h    = blockIdx.y;
    const int tid  = threadIdx.x;

    __shared__ float P[64 * 64];
    __shared__ float Wb[64][65];

#pragma unroll
    for (int s = 0; s < 16; s++) {
        int j = tid + s * 256;
        P[j] = proj[j];
        int r = j >> 6, c = j & 63;
        Wb[r][c] = W[(size_t)(dblk * 64 + r) * DIM_ + h * 64 + c];
    }
    __syncthreads();

    const int f  = tid & 63;
    const int ds = tid >> 6;
    for (int dl = ds; dl < 64; dl += 4) {
        float acc = 0.f;
#pragma unroll 16
        for (int dd = 0; dd < 64; dd++)
            acc = fmaf(Wb[dl][dd], P[dd * 64 + f], acc);
        Wp[(size_t)(dblk * 64 + dl) * DIM_ + h * 64 + f] = acc;
    }
}

// ---------------- zero scratch ----------------
__global__ void zero_kv_kernel()
{
    int i = blockIdx.x * 256 + threadIdx.x;
    if (i < 64 * 64 * 64) g_kv[i] = 0.f;
    if (i < 64 * 64) g_ksum[i] = 0.f;
}

// ---------------- kv[f,d] += sum_n kf[n,f]*v[n,d]; ksum[f] += sum_n kf[n,f] -------
// kf/v are fp16 column slices of the combined qkv buffer (leading dim ld).
__global__ __launch_bounds__(256) void kv_accum_kernel(
    const __half* __restrict__ kf, const __half* __restrict__ v, int ld)
{
    const int bh = blockIdx.y;
    const int b = bh >> 4, h = bh & 15;
    const int n0 = blockIdx.x * 1024;
    const int tid = threadIdx.x;

    __shared__ float kfs[32][64];
    __shared__ float vs[32][64];

    const int d  = tid & 63;
    const int fg = tid >> 6;

    float acc[16];
#pragma unroll
    for (int i = 0; i < 16; i++) acc[i] = 0.f;
    float ks = 0.f;

    for (int base = 0; base < 1024; base += 32) {
        // stage 32 rows x 64 cols of each, fp16 -> fp32
#pragma unroll
        for (int s = 0; s < 2; s++) {
            int j = tid + s * 256;          // 512 tasks: 256 kf chunks + 256 v chunks
            int which = j >> 8, cc = j & 255;
            int r = cc >> 3, c8 = (cc & 7) << 3;
            size_t row = (size_t)(b * N_ + n0 + base + r);
            const __half* src = (which ? v : kf) + row * ld + h * 64 + c8;
            uint4 raw = *(const uint4*)src;
            float* dst = (which ? &vs[r][c8] : &kfs[r][c8]);
            const __half2* hp = (const __half2*)&raw;
#pragma unroll
            for (int q = 0; q < 4; q++) {
                float2 f2 = __half22float2(hp[q]);
                dst[q * 2] = f2.x; dst[q * 2 + 1] = f2.y;
            }
        }
        __syncthreads();
#pragma unroll
        for (int r = 0; r < 32; r++) {
            float vd = vs[r][d];
#pragma unroll
            for (int i = 0; i < 16; i++)
                acc[i] = fmaf(kfs[r][fg * 16 + i], vd, acc[i]);
            if (tid < 64) ks += kfs[r][tid];
        }
        __syncthreads();
    }

#pragma unroll
    for (int i = 0; i < 16; i++)
        atomicAdd(&g_kv[(size_t)bh * 4096 + (fg * 16 + i) * 64 + d], acc[i]);
    if (tid < 64) atomicAdd(&g_ksum[bh * 64 + tid], ks);
}

// ---- attn = (qf @ kv) / (qf.ksum + EPS), qf fp16 in, attn fp16 out --------------
__global__ __launch_bounds__(256) void attn_out_kernel(
    const __half* __restrict__ qf, int ld,
    __half* __restrict__ outh)
{
    const int bh = blockIdx.y;
    const int b = bh >> 4, h = bh & 15;
    const int n0 = blockIdx.x * 64;
    const int tid = threadIdx.x;

    __shared__ float KVX[64][68];
    __shared__ float QF[64][68];

#pragma unroll
    for (int s = 0; s < 4; s++) {
        int j = tid + s * 256;
        int f = j >> 4, d4 = (j & 15) << 2;
        *(float4*)&KVX[f][d4] = *(const float4*)(g_kv + (size_t)bh * 4096 + f * 64 + d4);
    }
#pragma unroll
    for (int s = 0; s < 2; s++) {
        int j = tid + s * 256;             // 512 chunks of 8 halves
        int r = j >> 3, c8 = (j & 7) << 3;
        uint4 raw = *(const uint4*)(qf + (size_t)(b * N_ + n0 + r) * ld + h * 64 + c8);
        const __half2* hp = (const __half2*)&raw;
#pragma unroll
        for (int q = 0; q < 4; q++) {
            float2 f2 = __half22float2(hp[q]);
            QF[r][c8 + q * 2] = f2.x; QF[r][c8 + q * 2 + 1] = f2.y;
        }
    }
    if (tid < 64) KVX[tid][64] = g_ksum[bh * 64 + tid];
    __syncthreads();

    const int d4 = (tid & 15) << 2;
    const int rb = tid >> 4;
#pragma unroll
    for (int p = 0; p < 4; p++) {
        int r = p * 16 + rb;
        float4 num = make_float4(0.f, 0.f, 0.f, 0.f);
        float den = 0.f;
#pragma unroll 16
        for (int f = 0; f < 64; f++) {
            float q = QF[r][f];
            float4 kvv = *(float4*)&KVX[f][d4];
            num.x = fmaf(q, kvv.x, num.x);
            num.y = fmaf(q, kvv.y, num.y);
            num.z = fmaf(q, kvv.z, num.z);
            num.w = fmaf(q, kvv.w, num.w);
            den   = fmaf(q, KVX[f][64], den);
        }
        float inv = 1.f / (den + EPS);
        uint2 p2 = make_uint2(round2h(num.x * inv, num.y * inv),
                              round2h(num.z * inv, num.w * inv));
        size_t idx = (size_t)(b * N_ + n0 + r) * DIM_ + h * 64 + d4;
        *(uint2*)(outh + idx) = p2;
    }
}

// ---------------- launch ----------------
extern "C" void kernel_launch(void* const* d_in, const int* in_sizes, int n_in,
                              void* d_out, int out_size)
{
    const float* x    = (const float*)d_in[0];
    const float* Wq   = (const float*)d_in[1];
    const float* Wk   = (const float*)d_in[2];
    const float* Wv   = (const float*)d_in[3];
    const float* proj = (const float*)d_in[4];
    const float* Wo   = (const float*)d_in[5];
    const float* bo   = (const float*)d_in[6];
    float* out = (float*)d_out;

    __half *xh, *xl, *ah, *wc, *wo, *qkv;
    float *wqp, *wkp;
    cudaGetSymbolAddress((void**)&xh,  g_xh);
    cudaGetSymbolAddress((void**)&xl,  g_xl);
    cudaGetSymbolAddress((void**)&qkv, g_qkv);
    cudaGetSymbolAddress((void**)&ah,  g_ah);
    cudaGetSymbolAddress((void**)&wqp, g_wqp);
    cudaGetSymbolAddress((void**)&wkp, g_wkp);
    cudaGetSymbolAddress((void**)&wc,  g_wc);
    cudaGetSymbolAddress((void**)&wo,  g_wo);

    cudaFuncSetAttribute((const void*)gemm_pipe<3,1>,
                         cudaFuncAttributeMaxDynamicSharedMemorySize, GEMM_SMEM);
    cudaFuncSetAttribute((const void*)gemm_pipe<2,0>,
                         cudaFuncAttributeMaxDynamicSharedMemorySize, GEMM_SMEM);

    // fold proj into Wq / Wk
    dim3 fold_grid(16, 16);
    fold_kernel<<<fold_grid, 256>>>(Wq, proj, wqp);
    fold_kernel<<<fold_grid, 256>>>(Wk, proj, wkp);

    // convert operands: x split fp16 hi/lo; weights rounded to fp16
    split_kernel<<<BIG / 16 / 256, 256>>>(x, xh, xl, BIG / 4);
    const int W4 = DIM_ * DIM_ / 4;
    wconv_kernel<<<W4 / 256, 256>>>(wqp, wc, 0,    NQKV);
    wconv_kernel<<<W4 / 256, 256>>>(wkp, wc, 1024, NQKV);
    wconv_kernel<<<W4 / 256, 256>>>(Wv,  wc, 2048, NQKV);
    wconv_kernel<<<W4 / 256, 256>>>(Wo,  wo, 0,    DIM_);

    // merged QKV GEMM -> fp16 qkv; relu+eps on q,k cols; v block skips A-lo
    dim3 gq(NQKV / 128, M_ / 128);   // (24, 256)
    gemm_pipe<3,1><<<gq, 128, GEMM_SMEM>>>(xh, xl, wc, qkv, NQKV, NQKV, nullptr);

    // kv + ksum reduction (kf = cols 1024.., v = cols 2048..)
    zero_kv_kernel<<<1024, 256>>>();
    kv_accum_kernel<<<dim3(8, 64), 256>>>(qkv + 1024, qkv + 2048, NQKV);

    // numerator / denominator -> fp16 attn
    attn_out_kernel<<<dim3(128, 64), 256>>>(qkv, NQKV, ah);

    // output projection + bias (single fp16 A pass, fp32 out)
    dim3 go(DIM_ / 128, M_ / 128);   // (8, 256)
    gemm_pipe<2,0><<<go, 128, GEMM_SMEM>>>(ah, nullptr, wo, out, DIM_, DIM_, bo);
}

// round 13
// speedup vs baseline: 1.4129x; 1.2909x over previous
#include <cuda_runtime.h>
#include <cuda_bf16.h>
#include <cuda_fp16.h>
#include <cstdint>

#define EPS 1e-6f

// Shapes
#define B_ 4
#define N_ 8192
#define DIM_ 1024
#define H_ 16
#define M_ (B_ * N_)            // 32768 rows
#define BIG (M_ * DIM_)         // 33554432 elems
#define NQKV 3072

// ---------------- scratch (static device globals; no allocation) ----------------
__device__ __half g_xh[BIG];                            // x fp16 [M,1024]
__device__ __half g_qkv[(size_t)M_ * NQKV];             // [M, q|k|v] fp16
__device__ __half g_ah[BIG];                            // attn fp16 [M,1024]
__device__ float g_wqp[DIM_ * DIM_];
__device__ float g_wkp[DIM_ * DIM_];
__device__ __half g_wc[DIM_ * NQKV];                    // combined W [K,3072] fp16
__device__ __half g_wo[DIM_ * DIM_];                    // Wo [K,1024] fp16
__device__ float g_kv[64 * 64 * 64];   // [bh, f, d]
__device__ float g_ksum[64 * 64];      // [bh, f]

// ---------------- helpers ----------------
__device__ __forceinline__ uint32_t smem_u32(const void* p) {
    return (uint32_t)__cvta_generic_to_shared(p);
}

__device__ __forceinline__ void mma16816(float* c, const uint32_t* a, const uint32_t* b) {
    asm volatile(
        "mma.sync.aligned.m16n8k16.row.col.f32.f16.f16.f32 "
        "{%0,%1,%2,%3}, {%4,%5,%6,%7}, {%8,%9}, {%0,%1,%2,%3};\n"
        : "+f"(c[0]), "+f"(c[1]), "+f"(c[2]), "+f"(c[3])
        : "r"(a[0]), "r"(a[1]), "r"(a[2]), "r"(a[3]), "r"(b[0]), "r"(b[1]));
}

__device__ __forceinline__ void ldsm4(uint32_t* r, uint32_t addr) {
    asm volatile("ldmatrix.sync.aligned.m8n8.x4.shared.b16 {%0,%1,%2,%3}, [%4];"
        : "=r"(r[0]), "=r"(r[1]), "=r"(r[2]), "=r"(r[3]) : "r"(addr));
}
__device__ __forceinline__ void ldsm4t(uint32_t* r, uint32_t addr) {
    asm volatile("ldmatrix.sync.aligned.m8n8.x4.trans.shared.b16 {%0,%1,%2,%3}, [%4];"
        : "=r"(r[0]), "=r"(r[1]), "=r"(r[2]), "=r"(r[3]) : "r"(addr));
}

__device__ __forceinline__ void cp16(void* dst, const void* src) {
    asm volatile("cp.async.cg.shared.global [%0], [%1], 16;"
        :: "r"(smem_u32(dst)), "l"(src));
}
__device__ __forceinline__ void cp_commit() {
    asm volatile("cp.async.commit_group;");
}

__device__ __forceinline__ uint32_t round2h(float a, float b) {
    return (uint32_t)__half_as_ushort(__float2half_rn(a)) |
           ((uint32_t)__half_as_ushort(__float2half_rn(b)) << 16);
}

// ---------------- convert: fp32 -> fp16 (4 float4 per thread, MLP=4) ------------
__global__ __launch_bounds__(256) void xconv_kernel(
    const float* __restrict__ src, __half* __restrict__ h, int n4)
{
    int base = (blockIdx.x * 256 + threadIdx.x) * 4;
    if (base + 3 < n4) {
        float4 v0 = ((const float4*)src)[base + 0];
        float4 v1 = ((const float4*)src)[base + 1];
        float4 v2 = ((const float4*)src)[base + 2];
        float4 v3 = ((const float4*)src)[base + 3];
        ((uint2*)h)[base + 0] = make_uint2(round2h(v0.x, v0.y), round2h(v0.z, v0.w));
        ((uint2*)h)[base + 1] = make_uint2(round2h(v1.x, v1.y), round2h(v1.z, v1.w));
        ((uint2*)h)[base + 2] = make_uint2(round2h(v2.x, v2.y), round2h(v2.z, v2.w));
        ((uint2*)h)[base + 3] = make_uint2(round2h(v3.x, v3.y), round2h(v3.z, v3.w));
    }
}

// ---- round W[1024,1024] fp32 -> fp16 into buffer with leading dim ldout at col c0 ----
__global__ __launch_bounds__(256) void wconv_kernel(
    const float* __restrict__ W, __half* __restrict__ o, int c0, int ldout)
{
    int i = blockIdx.x * 256 + threadIdx.x;   // 262144 float4 tasks
    int r = i >> 8, c4 = (i & 255) << 2;
    float4 v = *(const float4*)(W + (size_t)r * DIM_ + c4);
    uint2 p = make_uint2(round2h(v.x, v.y), round2h(v.z, v.w));
    *(uint2*)(o + (size_t)r * ldout + c0 + c4) = p;
}

// ========== pipelined mma.sync GEMM: C[M, ldc] = A[M,1024] * B[1024, ldb] =======
// Pure fp16 operands (single pass), fp32 accumulate.
// BM=128, BN=128, BK=32, 128 threads (4 warps 2x2), warp tile 64x64, 3 stages.
// Smem 54 KB/CTA -> 3-4 CTAs/SM resident.
#define STAGES 3
#define ASTR 40                  // halves per A-smem row
#define A_STG (128 * ASTR)       // 5120 halves
#define B_STG (32 * 128)         // 4096 halves
#define GEMM_SMEM ((size_t)STAGES * (A_STG + B_STG) * 2)   // 55296 B

// EPI: 2 = fp32 out + bias, 3 = fp16 out, relu+EPS for col<2048
template<int EPI>
__global__ __launch_bounds__(128, 3) void gemm_pipe(
    const __half* __restrict__ Ag, const __half* __restrict__ Bg,
    void* __restrict__ Cv, int ldb, int ldc,
    const float* __restrict__ bias)
{
    extern __shared__ __half sm[];
    __half* Ah = sm;
    __half* Bh = Ah + STAGES * A_STG;

    const int tid  = threadIdx.x;
    const int lane = tid & 31;
    const int wid  = tid >> 5;          // 0..3
    const int g    = lane >> 2;
    const int t    = lane & 3;
    const int warp_m = (wid & 1) * 64;  // 0 or 64
    const int warp_n = (wid >> 1) * 64; // 0 or 64
    const int mb = blockIdx.y * 128;
    const int nb = blockIdx.x * 128;
    const int K = DIM_;

    float acc[4][8][4];
#pragma unroll
    for (int mi = 0; mi < 4; mi++)
#pragma unroll
        for (int ni = 0; ni < 8; ni++)
#pragma unroll
            for (int c = 0; c < 4; c++) acc[mi][ni][c] = 0.f;

    const int a_row_l  = (lane & 7) + ((lane >> 3) & 1) * 8;
    const int a_koff_l = ((lane >> 4) & 1) * 8;
    const int b_krow_l = (lane & 7) + ((lane >> 3) & 1) * 8;
    const int b_nchk_l = (lane >> 4) & 1;

    const int KT = K >> 5;   // 32

    auto load_stage = [&](int stg, int k0) {
        // A: 512 x 16B chunks: r=0..127, c=0..3
#pragma unroll
        for (int s = 0; s < 4; s++) {
            int j = tid + s * 128;
            int r = j >> 2, c = j & 3;
            cp16(Ah + stg * A_STG + r * ASTR + c * 8,
                 Ag + (size_t)(mb + r) * K + k0 + c * 8);
        }
        // B: 512 chunks: kk=0..31, c=0..15 (swizzled)
#pragma unroll
        for (int s = 0; s < 4; s++) {
            int j = tid + s * 128;
            int kk = j >> 4, c = j & 15;
            int cx = c ^ (kk & 7);
            cp16(Bh + stg * B_STG + kk * 128 + cx * 8,
                 Bg + (size_t)(k0 + kk) * ldb + nb + c * 8);
        }
        cp_commit();
    };

    int load_k = 0;
    for (; load_k < STAGES - 1; ++load_k) load_stage(load_k, load_k * 32);

    for (int i = 0; i < KT; i++) {
        asm volatile("cp.async.wait_group %0;" :: "n"(STAGES - 2));
        __syncthreads();
        if (load_k < KT) { load_stage(load_k % STAGES, load_k * 32); load_k++; }

        const int stg = i % STAGES;
        const __half* sAh = Ah + stg * A_STG;
        const __half* sBh = Bh + stg * B_STG;

#pragma unroll
        for (int ks = 0; ks < 2; ks++) {
            const int kb = ks * 16;
            uint32_t ah[4][4];
#pragma unroll
            for (int mi = 0; mi < 4; mi++) {
                int row = warp_m + mi * 16 + a_row_l;
                ldsm4(ah[mi], smem_u32(&sAh[row * ASTR + kb + a_koff_l]));
            }
#pragma unroll
            for (int np = 0; np < 4; np++) {
                const int krow  = kb + b_krow_l;
                const int chunk = ((warp_n + np * 16) >> 3) + b_nchk_l;
                const int cx    = chunk ^ (krow & 7);
                uint32_t bh[2][2], r4[4];
                ldsm4t(r4, smem_u32(&sBh[krow * 128 + cx * 8]));
                bh[0][0] = r4[0]; bh[0][1] = r4[1]; bh[1][0] = r4[2]; bh[1][1] = r4[3];
#pragma unroll
                for (int mi = 0; mi < 4; mi++)
#pragma unroll
                    for (int q = 0; q < 2; q++)
                        mma16816(acc[mi][np * 2 + q], ah[mi], bh[q]);
            }
        }
    }

    // ---- epilogue ----
#pragma unroll
    for (int mi = 0; mi < 4; mi++) {
        int r0 = mb + warp_m + mi * 16 + g;
#pragma unroll
        for (int ni = 0; ni < 8; ni++) {
            int col = nb + warp_n + ni * 8 + 2 * t;
            float2 v0 = make_float2(acc[mi][ni][0], acc[mi][ni][1]);
            float2 v1 = make_float2(acc[mi][ni][2], acc[mi][ni][3]);
            if (EPI == 3) {
                if (col < 2048) {
                    v0.x = fmaxf(v0.x, 0.f) + EPS; v0.y = fmaxf(v0.y, 0.f) + EPS;
                    v1.x = fmaxf(v1.x, 0.f) + EPS; v1.y = fmaxf(v1.y, 0.f) + EPS;
                }
                __half* Ch = (__half*)Cv;
                *(uint32_t*)(Ch + (size_t)r0 * ldc + col)       = round2h(v0.x, v0.y);
                *(uint32_t*)(Ch + (size_t)(r0 + 8) * ldc + col) = round2h(v1.x, v1.y);
            } else {
                float* C = (float*)Cv;
                float b0 = bias[col], b1 = bias[col + 1];
                v0.x += b0; v0.y += b1; v1.x += b0; v1.y += b1;
                *(float2*)(C + (size_t)r0 * ldc + col)       = v0;
                *(float2*)(C + (size_t)(r0 + 8) * ldc + col) = v1;
            }
        }
    }
}

// ---------------- fold: Wp[:, h*64+f] = W[:, h*64+:] @ proj ----------------
__global__ __launch_bounds__(256) void fold_kernel(
    const float* __restrict__ W, const float* __restrict__ proj,
    float* __restrict__ Wp)
{
    const int dblk = blockIdx.x;
    const int h    = blockIdx.y;
    const int tid  = threadIdx.x;

    __shared__ float P[64 * 64];
    __shared__ float Wb[64][65];

#pragma unroll
    for (int s = 0; s < 16; s++) {
        int j = tid + s * 256;
        P[j] = proj[j];
        int r = j >> 6, c = j & 63;
        Wb[r][c] = W[(size_t)(dblk * 64 + r) * DIM_ + h * 64 + c];
    }
    __syncthreads();

    const int f  = tid & 63;
    const int ds = tid >> 6;
    for (int dl = ds; dl < 64; dl += 4) {
        float acc = 0.f;
#pragma unroll 16
        for (int dd = 0; dd < 64; dd++)
            acc = fmaf(Wb[dl][dd], P[dd * 64 + f], acc);
        Wp[(size_t)(dblk * 64 + dl) * DIM_ + h * 64 + f] = acc;
    }
}

// ---------------- zero scratch ----------------
__global__ void zero_kv_kernel()
{
    int i = blockIdx.x * 256 + threadIdx.x;
    if (i < 64 * 64 * 64) g_kv[i] = 0.f;
    if (i < 64 * 64) g_ksum[i] = 0.f;
}

// ---------------- kv[f,d] += sum_n kf[n,f]*v[n,d]; ksum[f] += sum_n kf[n,f] -------
// kf/v are fp16 column slices of the combined qkv buffer (leading dim ld).
__global__ __launch_bounds__(256) void kv_accum_kernel(
    const __half* __restrict__ kf, const __half* __restrict__ v, int ld)
{
    const int bh = blockIdx.y;
    const int b = bh >> 4, h = bh & 15;
    const int n0 = blockIdx.x * 1024;
    const int tid = threadIdx.x;

    __shared__ float kfs[32][64];
    __shared__ float vs[32][64];

    const int d  = tid & 63;
    const int fg = tid >> 6;

    float acc[16];
#pragma unroll
    for (int i = 0; i < 16; i++) acc[i] = 0.f;
    float ks = 0.f;

    for (int base = 0; base < 1024; base += 32) {
#pragma unroll
        for (int s = 0; s < 2; s++) {
            int j = tid + s * 256;          // 512 tasks: 256 kf chunks + 256 v chunks
            int which = j >> 8, cc = j & 255;
            int r = cc >> 3, c8 = (cc & 7) << 3;
            size_t row = (size_t)(b * N_ + n0 + base + r);
            const __half* src = (which ? v : kf) + row * ld + h * 64 + c8;
            uint4 raw = *(const uint4*)src;
            float* dst = (which ? &vs[r][c8] : &kfs[r][c8]);
            const __half2* hp = (const __half2*)&raw;
#pragma unroll
            for (int q = 0; q < 4; q++) {
                float2 f2 = __half22float2(hp[q]);
                dst[q * 2] = f2.x; dst[q * 2 + 1] = f2.y;
            }
        }
        __syncthreads();
#pragma unroll
        for (int r = 0; r < 32; r++) {
            float vd = vs[r][d];
#pragma unroll
            for (int i = 0; i < 16; i++)
                acc[i] = fmaf(kfs[r][fg * 16 + i], vd, acc[i]);
            if (tid < 64) ks += kfs[r][tid];
        }
        __syncthreads();
    }

#pragma unroll
    for (int i = 0; i < 16; i++)
        atomicAdd(&g_kv[(size_t)bh * 4096 + (fg * 16 + i) * 64 + d], acc[i]);
    if (tid < 64) atomicAdd(&g_ksum[bh * 64 + tid], ks);
}

// ---- attn = (qf @ kv) / (qf.ksum + EPS), qf fp16 in, attn fp16 out --------------
__global__ __launch_bounds__(256) void attn_out_kernel(
    const __half* __restrict__ qf, int ld,
    __half* __restrict__ outh)
{
    const int bh = blockIdx.y;
    const int b = bh >> 4, h = bh & 15;
    const int n0 = blockIdx.x * 64;
    const int tid = threadIdx.x;

    __shared__ float KVX[64][68];
    __shared__ float QF[64][68];

#pragma unroll
    for (int s = 0; s < 4; s++) {
        int j = tid + s * 256;
        int f = j >> 4, d4 = (j & 15) << 2;
        *(float4*)&KVX[f][d4] = *(const float4*)(g_kv + (size_t)bh * 4096 + f * 64 + d4);
    }
#pragma unroll
    for (int s = 0; s < 2; s++) {
        int j = tid + s * 256;             // 512 chunks of 8 halves
        int r = j >> 3, c8 = (j & 7) << 3;
        uint4 raw = *(const uint4*)(qf + (size_t)(b * N_ + n0 + r) * ld + h * 64 + c8);
        const __half2* hp = (const __half2*)&raw;
#pragma unroll
        for (int q = 0; q < 4; q++) {
            float2 f2 = __half22float2(hp[q]);
            QF[r][c8 + q * 2] = f2.x; QF[r][c8 + q * 2 + 1] = f2.y;
        }
    }
    if (tid < 64) KVX[tid][64] = g_ksum[bh * 64 + tid];
    __syncthreads();

    const int d4 = (tid & 15) << 2;
    const int rb = tid >> 4;
#pragma unroll
    for (int p = 0; p < 4; p++) {
        int r = p * 16 + rb;
        float4 num = make_float4(0.f, 0.f, 0.f, 0.f);
        float den = 0.f;
#pragma unroll 16
        for (int f = 0; f < 64; f++) {
            float q = QF[r][f];
            float4 kvv = *(float4*)&KVX[f][d4];
            num.x = fmaf(q, kvv.x, num.x);
            num.y = fmaf(q, kvv.y, num.y);
            num.z = fmaf(q, kvv.z, num.z);
            num.w = fmaf(q, kvv.w, num.w);
            den   = fmaf(q, KVX[f][64], den);
        }
        float inv = 1.f / (den + EPS);
        uint2 p2 = make_uint2(round2h(num.x * inv, num.y * inv),
                              round2h(num.z * inv, num.w * inv));
        size_t idx = (size_t)(b * N_ + n0 + r) * DIM_ + h * 64 + d4;
        *(uint2*)(outh + idx) = p2;
    }
}

// ---------------- launch ----------------
extern "C" void kernel_launch(void* const* d_in, const int* in_sizes, int n_in,
                              void* d_out, int out_size)
{
    const float* x    = (const float*)d_in[0];
    const float* Wq   = (const float*)d_in[1];
    const float* Wk   = (const float*)d_in[2];
    const float* Wv   = (const float*)d_in[3];
    const float* proj = (const float*)d_in[4];
    const float* Wo   = (const float*)d_in[5];
    const float* bo   = (const float*)d_in[6];
    float* out = (float*)d_out;

    __half *xh, *ah, *wc, *wo, *qkv;
    float *wqp, *wkp;
    cudaGetSymbolAddress((void**)&xh,  g_xh);
    cudaGetSymbolAddress((void**)&qkv, g_qkv);
    cudaGetSymbolAddress((void**)&ah,  g_ah);
    cudaGetSymbolAddress((void**)&wqp, g_wqp);
    cudaGetSymbolAddress((void**)&wkp, g_wkp);
    cudaGetSymbolAddress((void**)&wc,  g_wc);
    cudaGetSymbolAddress((void**)&wo,  g_wo);

    cudaFuncSetAttribute((const void*)gemm_pipe<3>,
                         cudaFuncAttributeMaxDynamicSharedMemorySize, GEMM_SMEM);
    cudaFuncSetAttribute((const void*)gemm_pipe<2>,
                         cudaFuncAttributeMaxDynamicSharedMemorySize, GEMM_SMEM);

    // fold proj into Wq / Wk
    dim3 fold_grid(16, 16);
    fold_kernel<<<fold_grid, 256>>>(Wq, proj, wqp);
    fold_kernel<<<fold_grid, 256>>>(Wk, proj, wkp);

    // convert operands to fp16
    xconv_kernel<<<BIG / 16 / 256, 256>>>(x, xh, BIG / 4);
    const int W4 = DIM_ * DIM_ / 4;
    wconv_kernel<<<W4 / 256, 256>>>(wqp, wc, 0,    NQKV);
    wconv_kernel<<<W4 / 256, 256>>>(wkp, wc, 1024, NQKV);
    wconv_kernel<<<W4 / 256, 256>>>(Wv,  wc, 2048, NQKV);
    wconv_kernel<<<W4 / 256, 256>>>(Wo,  wo, 0,    DIM_);

    // merged QKV GEMM -> fp16 qkv; relu+eps on q,k cols
    dim3 gq(NQKV / 128, M_ / 128);   // (24, 256)
    gemm_pipe<3><<<gq, 128, GEMM_SMEM>>>(xh, wc, qkv, NQKV, NQKV, nullptr);

    // kv + ksum reduction (kf = cols 1024.., v = cols 2048..)
    zero_kv_kernel<<<1024, 256>>>();
    kv_accum_kernel<<<dim3(8, 64), 256>>>(qkv + 1024, qkv + 2048, NQKV);

    // numerator / denominator -> fp16 attn
    attn_out_kernel<<<dim3(128, 64), 256>>>(qkv, NQKV, ah);

    // output projection + bias (fp32 out)
    dim3 go(DIM_ / 128, M_ / 128);   // (8, 256)
    gemm_pipe<2><<<go, 128, GEMM_SMEM>>>(ah, wo, out, DIM_, DIM_, bo);
}

// round 16
// speedup vs baseline: 1.8560x; 1.3135x over previous
#include <cuda_runtime.h>
#include <cuda_bf16.h>
#include <cuda_fp16.h>
#include <cstdint>

#define EPS 1e-6f

// Shapes
#define B_ 4
#define N_ 8192
#define DIM_ 1024
#define H_ 16
#define M_ (B_ * N_)            // 32768 rows
#define BIG (M_ * DIM_)         // 33554432 elems
#define NQKV 3072

// ---------------- scratch (static device globals; no allocation) ----------------
__device__ __half g_xh[BIG];                            // x fp16 [M,1024]
__device__ __half g_qkv[(size_t)M_ * NQKV];             // [M, q|k|v] fp16
__device__ __half g_ah[BIG];                            // attn fp16 [M,1024]
__device__ float g_wqp[DIM_ * DIM_];
__device__ float g_wkp[DIM_ * DIM_];
__device__ __half g_wc[DIM_ * NQKV];                    // combined W [K,3072] fp16
__device__ __half g_wo[DIM_ * DIM_];                    // Wo [K,1024] fp16
__device__ float g_kv[64 * 64 * 64];   // [bh, f, d]
__device__ float g_ksum[64 * 64];      // [bh, f]

// ---------------- helpers ----------------
__device__ __forceinline__ uint32_t smem_u32(const void* p) {
    return (uint32_t)__cvta_generic_to_shared(p);
}

__device__ __forceinline__ void mma16816(float* c, const uint32_t* a, const uint32_t* b) {
    asm volatile(
        "mma.sync.aligned.m16n8k16.row.col.f32.f16.f16.f32 "
        "{%0,%1,%2,%3}, {%4,%5,%6,%7}, {%8,%9}, {%0,%1,%2,%3};\n"
        : "+f"(c[0]), "+f"(c[1]), "+f"(c[2]), "+f"(c[3])
        : "r"(a[0]), "r"(a[1]), "r"(a[2]), "r"(a[3]), "r"(b[0]), "r"(b[1]));
}

__device__ __forceinline__ void ldsm4(uint32_t* r, uint32_t addr) {
    asm volatile("ldmatrix.sync.aligned.m8n8.x4.shared.b16 {%0,%1,%2,%3}, [%4];"
        : "=r"(r[0]), "=r"(r[1]), "=r"(r[2]), "=r"(r[3]) : "r"(addr));
}
__device__ __forceinline__ void ldsm4t(uint32_t* r, uint32_t addr) {
    asm volatile("ldmatrix.sync.aligned.m8n8.x4.trans.shared.b16 {%0,%1,%2,%3}, [%4];"
        : "=r"(r[0]), "=r"(r[1]), "=r"(r[2]), "=r"(r[3]) : "r"(addr));
}

__device__ __forceinline__ void cp16(void* dst, const void* src) {
    asm volatile("cp.async.cg.shared.global [%0], [%1], 16;"
        :: "r"(smem_u32(dst)), "l"(src));
}
__device__ __forceinline__ void cp_commit() {
    asm volatile("cp.async.commit_group;");
}

__device__ __forceinline__ uint32_t round2h(float a, float b) {
    return (uint32_t)__half_as_ushort(__float2half_rn(a)) |
           ((uint32_t)__half_as_ushort(__float2half_rn(b)) << 16);
}

// ---------------- convert: fp32 -> fp16 (4 float4 per thread, MLP=4) ------------
__global__ __launch_bounds__(256) void xconv_kernel(
    const float* __restrict__ src, __half* __restrict__ h, int n4)
{
    int base = (blockIdx.x * 256 + threadIdx.x) * 4;
    if (base + 3 < n4) {
        float4 v0 = ((const float4*)src)[base + 0];
        float4 v1 = ((const float4*)src)[base + 1];
        float4 v2 = ((const float4*)src)[base + 2];
        float4 v3 = ((const float4*)src)[base + 3];
        ((uint2*)h)[base + 0] = make_uint2(round2h(v0.x, v0.y), round2h(v0.z, v0.w));
        ((uint2*)h)[base + 1] = make_uint2(round2h(v1.x, v1.y), round2h(v1.z, v1.w));
        ((uint2*)h)[base + 2] = make_uint2(round2h(v2.x, v2.y), round2h(v2.z, v2.w));
        ((uint2*)h)[base + 3] = make_uint2(round2h(v3.x, v3.y), round2h(v3.z, v3.w));
    }
}

// ---- round W[1024,1024] fp32 -> fp16 into buffer with leading dim ldout at col c0 ----
__global__ __launch_bounds__(256) void wconv_kernel(
    const float* __restrict__ W, __half* __restrict__ o, int c0, int ldout)
{
    int i = blockIdx.x * 256 + threadIdx.x;
    int r = i >> 8, c4 = (i & 255) << 2;
    float4 v = *(const float4*)(W + (size_t)r * DIM_ + c4);
    uint2 p = make_uint2(round2h(v.x, v.y), round2h(v.z, v.w));
    *(uint2*)(o + (size_t)r * ldout + c0 + c4) = p;
}

// ========== pipelined mma.sync GEMM (unchanged, proven) =========================
#define STAGES 3
#define ASTR 40
#define A_STG (128 * ASTR)
#define B_STG (32 * 128)
#define GEMM_SMEM ((size_t)STAGES * (A_STG + B_STG) * 2)   // 55296 B

template<int EPI>   // 2 = fp32 out + bias, 3 = fp16 out, relu+EPS for col<2048
__global__ __launch_bounds__(128, 3) void gemm_pipe(
    const __half* __restrict__ Ag, const __half* __restrict__ Bg,
    void* __restrict__ Cv, int ldb, int ldc,
    const float* __restrict__ bias)
{
    extern __shared__ __half sm[];
    __half* Ah = sm;
    __half* Bh = Ah + STAGES * A_STG;

    const int tid  = threadIdx.x;
    const int lane = tid & 31;
    const int wid  = tid >> 5;
    const int g    = lane >> 2;
    const int t    = lane & 3;
    const int warp_m = (wid & 1) * 64;
    const int warp_n = (wid >> 1) * 64;
    const int mb = blockIdx.y * 128;
    const int nb = blockIdx.x * 128;
    const int K = DIM_;

    float acc[4][8][4];
#pragma unroll
    for (int mi = 0; mi < 4; mi++)
#pragma unroll
        for (int ni = 0; ni < 8; ni++)
#pragma unroll
            for (int c = 0; c < 4; c++) acc[mi][ni][c] = 0.f;

    const int a_row_l  = (lane & 7) + ((lane >> 3) & 1) * 8;
    const int a_koff_l = ((lane >> 4) & 1) * 8;
    const int b_krow_l = (lane & 7) + ((lane >> 3) & 1) * 8;
    const int b_nchk_l = (lane >> 4) & 1;

    const int KT = K >> 5;

    auto load_stage = [&](int stg, int k0) {
#pragma unroll
        for (int s = 0; s < 4; s++) {
            int j = tid + s * 128;
            int r = j >> 2, c = j & 3;
            cp16(Ah + stg * A_STG + r * ASTR + c * 8,
                 Ag + (size_t)(mb + r) * K + k0 + c * 8);
        }
#pragma unroll
        for (int s = 0; s < 4; s++) {
            int j = tid + s * 128;
            int kk = j >> 4, c = j & 15;
            int cx = c ^ (kk & 7);
            cp16(Bh + stg * B_STG + kk * 128 + cx * 8,
                 Bg + (size_t)(k0 + kk) * ldb + nb + c * 8);
        }
        cp_commit();
    };

    int load_k = 0;
    for (; load_k < STAGES - 1; ++load_k) load_stage(load_k, load_k * 32);

    for (int i = 0; i < KT; i++) {
        asm volatile("cp.async.wait_group %0;" :: "n"(STAGES - 2));
        __syncthreads();
        if (load_k < KT) { load_stage(load_k % STAGES, load_k * 32); load_k++; }

        const int stg = i % STAGES;
        const __half* sAh = Ah + stg * A_STG;
        const __half* sBh = Bh + stg * B_STG;

#pragma unroll
        for (int ks = 0; ks < 2; ks++) {
            const int kb = ks * 16;
            uint32_t ah[4][4];
#pragma unroll
            for (int mi = 0; mi < 4; mi++) {
                int row = warp_m + mi * 16 + a_row_l;
                ldsm4(ah[mi], smem_u32(&sAh[row * ASTR + kb + a_koff_l]));
            }
#pragma unroll
            for (int np = 0; np < 4; np++) {
                const int krow  = kb + b_krow_l;
                const int chunk = ((warp_n + np * 16) >> 3) + b_nchk_l;
                const int cx    = chunk ^ (krow & 7);
                uint32_t bh[2][2], r4[4];
                ldsm4t(r4, smem_u32(&sBh[krow * 128 + cx * 8]));
                bh[0][0] = r4[0]; bh[0][1] = r4[1]; bh[1][0] = r4[2]; bh[1][1] = r4[3];
#pragma unroll
                for (int mi = 0; mi < 4; mi++)
#pragma unroll
                    for (int q = 0; q < 2; q++)
                        mma16816(acc[mi][np * 2 + q], ah[mi], bh[q]);
            }
        }
    }

#pragma unroll
    for (int mi = 0; mi < 4; mi++) {
        int r0 = mb + warp_m + mi * 16 + g;
#pragma unroll
        for (int ni = 0; ni < 8; ni++) {
            int col = nb + warp_n + ni * 8 + 2 * t;
            float2 v0 = make_float2(acc[mi][ni][0], acc[mi][ni][1]);
            float2 v1 = make_float2(acc[mi][ni][2], acc[mi][ni][3]);
            if (EPI == 3) {
                if (col < 2048) {
                    v0.x = fmaxf(v0.x, 0.f) + EPS; v0.y = fmaxf(v0.y, 0.f) + EPS;
                    v1.x = fmaxf(v1.x, 0.f) + EPS; v1.y = fmaxf(v1.y, 0.f) + EPS;
                }
                __half* Ch = (__half*)Cv;
                *(uint32_t*)(Ch + (size_t)r0 * ldc + col)       = round2h(v0.x, v0.y);
                *(uint32_t*)(Ch + (size_t)(r0 + 8) * ldc + col) = round2h(v1.x, v1.y);
            } else {
                float* C = (float*)Cv;
                float b0 = bias[col], b1 = bias[col + 1];
                v0.x += b0; v0.y += b1; v1.x += b0; v1.y += b1;
                *(float2*)(C + (size_t)r0 * ldc + col)       = v0;
                *(float2*)(C + (size_t)(r0 + 8) * ldc + col) = v1;
            }
        }
    }
}

// ---------------- fold: Wp[:, h*64+f] = W[:, h*64+:] @ proj ----------------
__global__ __launch_bounds__(256) void fold_kernel(
    const float* __restrict__ W, const float* __restrict__ proj,
    float* __restrict__ Wp)
{
    const int dblk = blockIdx.x;
    const int h    = blockIdx.y;
    const int tid  = threadIdx.x;

    __shared__ float P[64 * 64];
    __shared__ float Wb[64][65];

#pragma unroll
    for (int s = 0; s < 16; s++) {
        int j = tid + s * 256;
        P[j] = proj[j];
        int r = j >> 6, c = j & 63;
        Wb[r][c] = W[(size_t)(dblk * 64 + r) * DIM_ + h * 64 + c];
    }
    __syncthreads();

    const int f  = tid & 63;
    const int ds = tid >> 6;
    for (int dl = ds; dl < 64; dl += 4) {
        float acc = 0.f;
#pragma unroll 16
        for (int dd = 0; dd < 64; dd++)
            acc = fmaf(Wb[dl][dd], P[dd * 64 + f], acc);
        Wp[(size_t)(dblk * 64 + dl) * DIM_ + h * 64 + f] = acc;
    }
}

// ---------------- zero scratch ----------------
__global__ void zero_kv_kernel()
{
    int i = blockIdx.x * 256 + threadIdx.x;
    if (i < 64 * 64 * 64) g_kv[i] = 0.f;
    if (i < 64 * 64) g_ksum[i] = 0.f;
}

// ---- kv[f,d] += sum_n kf[n,f]*v[n,d]; ksum[f] += sum_n kf[n,f] (R12-proven) ----
__global__ __launch_bounds__(256) void kv_accum_kernel(
    const __half* __restrict__ kf, const __half* __restrict__ v, int ld)
{
    const int bh = blockIdx.y;
    const int b = bh >> 4, h = bh & 15;
    const int n0 = blockIdx.x * 1024;
    const int tid = threadIdx.x;

    __shared__ float kfs[32][64];
    __shared__ float vs[32][64];

    const int d  = tid & 63;
    const int fg = tid >> 6;

    float acc[16];
#pragma unroll
    for (int i = 0; i < 16; i++) acc[i] = 0.f;
    float ks = 0.f;

    for (int base = 0; base < 1024; base += 32) {
#pragma unroll
        for (int s = 0; s < 2; s++) {
            int j = tid + s * 256;          // 512 tasks: 256 kf chunks + 256 v chunks
            int which = j >> 8, cc = j & 255;
            int r = cc >> 3, c8 = (cc & 7) << 3;
            size_t row = (size_t)(b * N_ + n0 + base + r);
            const __half* src = (which ? v : kf) + row * ld + h * 64 + c8;
            uint4 raw = *(const uint4*)src;
            float* dst = (which ? &vs[r][c8] : &kfs[r][c8]);
            const __half2* hp = (const __half2*)&raw;
#pragma unroll
            for (int q = 0; q < 4; q++) {
                float2 f2 = __half22float2(hp[q]);
                dst[q * 2] = f2.x; dst[q * 2 + 1] = f2.y;
            }
        }
        __syncthreads();
#pragma unroll
        for (int r = 0; r < 32; r++) {
            float vd = vs[r][d];
#pragma unroll
            for (int i = 0; i < 16; i++)
                acc[i] = fmaf(kfs[r][fg * 16 + i], vd, acc[i]);
            if (tid < 64) ks += kfs[r][tid];
        }
        __syncthreads();
    }

#pragma unroll
    for (int i = 0; i < 16; i++)
        atomicAdd(&g_kv[(size_t)bh * 4096 + (fg * 16 + i) * 64 + d], acc[i]);
    if (tid < 64) atomicAdd(&g_ksum[bh * 64 + tid], ks);
}

// ======== attn_mma: attn = (qf @ kv) / (qf . ksum + EPS) via tensor cores ========
// A = qf [128 rows x 64 f] (standard non-trans), B = kv [f][d] (standard trans-B).
// grid (N_/128 row blocks PER BATCH, 64 bh). 128 thr, 4 warps (m32 each). K=64.
__global__ __launch_bounds__(128) void attn_mma_kernel(
    const __half* __restrict__ qkv_, __half* __restrict__ outh)
{
    __shared__ __align__(16) __half sq[128 * 64];
    __shared__ __align__(16) __half skv[64 * 64];
    __shared__ float ksm[64];
    __shared__ float sden[128];

    const int bh = blockIdx.y;
    const int b = bh >> 4, h = bh & 15;
    const int r0g = blockIdx.x * 128;     // row block WITHIN batch
    const int tid = threadIdx.x;
    const int lane = tid & 31;
    const int wid = tid >> 5;
    const int g = lane >> 2;
    const int t = lane & 3;
    const int warp_m = wid * 32;

    // stage qf via cp.async (1024 x 16B chunks, swizzled)
#pragma unroll
    for (int s = 0; s < 8; s++) {
        int j = tid + s * 128;
        int r = j >> 3, c = j & 7;
        int cx = c ^ (r & 7);
        cp16(&sq[r * 64 + cx * 8],
             qkv_ + (size_t)(b * N_ + r0g + r) * NQKV + h * 64 + c * 8);
    }
    cp_commit();

    // stage kv fp32 -> fp16 (swizzled [f][d]) and ksum
    const float* kvp = g_kv + (size_t)bh * 4096;
#pragma unroll
    for (int s = 0; s < 16; s++) {
        int j = tid + s * 128;          // 2048 float2 tasks
        int f = j >> 5, dp = (j & 31) * 2;
        float2 w = *(const float2*)(kvp + f * 64 + dp);
        int cx = (dp >> 3) ^ (f & 7);
        *(uint32_t*)&skv[f * 64 + cx * 8 + (dp & 7)] = round2h(w.x, w.y);
    }
    if (tid < 64) ksm[tid] = g_ksum[bh * 64 + tid];

    asm volatile("cp.async.wait_group 0;");
    __syncthreads();

    // den[r] = sum_f qf[r,f] * ksum[f] + EPS (per-thread row)
    {
        float den = 0.f;
#pragma unroll
        for (int c = 0; c < 8; c++) {
            int cx = c ^ (tid & 7);
            uint4 q4 = *(uint4*)&sq[tid * 64 + cx * 8];
            const __half2* hp = (const __half2*)&q4;
#pragma unroll
            for (int q = 0; q < 4; q++) {
                float2 f2 = __half22float2(hp[q]);
                den = fmaf(f2.x, ksm[c * 8 + q * 2],     den);
                den = fmaf(f2.y, ksm[c * 8 + q * 2 + 1], den);
            }
        }
        sden[tid] = den + EPS;
    }
    __syncthreads();

    // MMA: C[128 x 64] = qf @ kv
    float acc[2][8][4];
#pragma unroll
    for (int mi = 0; mi < 2; mi++)
#pragma unroll
        for (int ni = 0; ni < 8; ni++)
#pragma unroll
            for (int c = 0; c < 4; c++) acc[mi][ni][c] = 0.f;

    const int a_row_l = (lane & 7) + ((lane >> 3) & 1) * 8;
    const int a_kchk  = (lane >> 4) & 1;
    const int b_krow_l = (lane & 7) + ((lane >> 3) & 1) * 8;
    const int b_nchk_l = (lane >> 4) & 1;

#pragma unroll
    for (int ks = 0; ks < 4; ks++) {
        const int kb = ks * 16;
        uint32_t ah[2][4];
#pragma unroll
        for (int mi = 0; mi < 2; mi++) {
            int row = warp_m + mi * 16 + a_row_l;
            int achk = ((kb >> 3) + a_kchk) ^ (row & 7);
            ldsm4(ah[mi], smem_u32(&sq[row * 64 + achk * 8]));
        }
#pragma unroll
        for (int np = 0; np < 4; np++) {
            const int krow = kb + b_krow_l;
            const int chk  = ((np * 16) >> 3) + b_nchk_l;
            const int cx   = chk ^ (krow & 7);
            uint32_t r4[4], bfr[2][2];
            ldsm4t(r4, smem_u32(&skv[krow * 64 + cx * 8]));
            bfr[0][0] = r4[0]; bfr[0][1] = r4[1];
            bfr[1][0] = r4[2]; bfr[1][1] = r4[3];
#pragma unroll
            for (int mi = 0; mi < 2; mi++) {
                mma16816(acc[mi][np * 2],     ah[mi], bfr[0]);
                mma16816(acc[mi][np * 2 + 1], ah[mi], bfr[1]);
            }
        }
    }

    // epilogue: divide by den, round fp16, store
#pragma unroll
    for (int mi = 0; mi < 2; mi++) {
        int lr = warp_m + mi * 16 + g;
        float inv0 = 1.f / sden[lr];
        float inv1 = 1.f / sden[lr + 8];
        size_t row0 = (size_t)(b * N_ + r0g + lr) * DIM_ + h * 64;
        size_t row1 = row0 + 8 * DIM_;
#pragma unroll
        for (int ni = 0; ni < 8; ni++) {
            int col = ni * 8 + 2 * t;
            *(uint32_t*)(outh + row0 + col) =
                round2h(acc[mi][ni][0] * inv0, acc[mi][ni][1] * inv0);
            *(uint32_t*)(outh + row1 + col) =
                round2h(acc[mi][ni][2] * inv1, acc[mi][ni][3] * inv1);
        }
    }
}

// ---------------- launch ----------------
extern "C" void kernel_launch(void* const* d_in, const int* in_sizes, int n_in,
                              void* d_out, int out_size)
{
    const float* x    = (const float*)d_in[0];
    const float* Wq   = (const float*)d_in[1];
    const float* Wk   = (const float*)d_in[2];
    const float* Wv   = (const float*)d_in[3];
    const float* proj = (const float*)d_in[4];
    const float* Wo   = (const float*)d_in[5];
    const float* bo   = (const float*)d_in[6];
    float* out = (float*)d_out;

    __half *xh, *ah, *wc, *wo, *qkv;
    float *wqp, *wkp;
    cudaGetSymbolAddress((void**)&xh,  g_xh);
    cudaGetSymbolAddress((void**)&qkv, g_qkv);
    cudaGetSymbolAddress((void**)&ah,  g_ah);
    cudaGetSymbolAddress((void**)&wqp, g_wqp);
    cudaGetSymbolAddress((void**)&wkp, g_wkp);
    cudaGetSymbolAddress((void**)&wc,  g_wc);
    cudaGetSymbolAddress((void**)&wo,  g_wo);

    cudaFuncSetAttribute((const void*)gemm_pipe<3>,
                         cudaFuncAttributeMaxDynamicSharedMemorySize, GEMM_SMEM);
    cudaFuncSetAttribute((const void*)gemm_pipe<2>,
                         cudaFuncAttributeMaxDynamicSharedMemorySize, GEMM_SMEM);

    // fold proj into Wq / Wk
    dim3 fold_grid(16, 16);
    fold_kernel<<<fold_grid, 256>>>(Wq, proj, wqp);
    fold_kernel<<<fold_grid, 256>>>(Wk, proj, wkp);

    // convert operands to fp16
    xconv_kernel<<<BIG / 16 / 256, 256>>>(x, xh, BIG / 4);
    const int W4 = DIM_ * DIM_ / 4;
    wconv_kernel<<<W4 / 256, 256>>>(wqp, wc, 0,    NQKV);
    wconv_kernel<<<W4 / 256, 256>>>(wkp, wc, 1024, NQKV);
    wconv_kernel<<<W4 / 256, 256>>>(Wv,  wc, 2048, NQKV);
    wconv_kernel<<<W4 / 256, 256>>>(Wo,  wo, 0,    DIM_);

    // merged QKV GEMM -> fp16 qkv; relu+eps on q,k cols
    dim3 gq(NQKV / 128, M_ / 128);   // (24, 256)
    gemm_pipe<3><<<gq, 128, GEMM_SMEM>>>(xh, wc, qkv, NQKV, NQKV, nullptr);

    // kv + ksum reduction (scalar, R12-proven)
    zero_kv_kernel<<<1024, 256>>>();
    kv_accum_kernel<<<dim3(8, 64), 256>>>(qkv + 1024, qkv + 2048, NQKV);

    // attn = num/den via tensor cores -> fp16 (grid.x per batch)
    attn_mma_kernel<<<dim3(N_ / 128, 64), 128>>>(qkv, ah);

    // output projection + bias (fp32 out)
    dim3 go(DIM_ / 128, M_ / 128);   // (8, 256)
    gemm_pipe<2><<<go, 128, GEMM_SMEM>>>(ah, wo, out, DIM_, DIM_, bo);
}